// round 1
// baseline (speedup 1.0000x reference)
#include <cuda_runtime.h>

// ---------------------------------------------------------------------------
// Problem constants
// ---------------------------------------------------------------------------
#define SEQ      1024
#define NB       16
#define NHEADS   8
#define DIN      512
#define KDIM     64
#define PROJ_N   2048               // 512 Q + 512 K + 1024 V columns
#define ROWS     (NB * SEQ)         // 16384
#define ATTN_PAD 68                 // smem row stride (multiple of 4 for float4)
#define ATTN_SMEM (5 * 64 * ATTN_PAD * 4)

// ---------------------------------------------------------------------------
// Static scratch (allowed: __device__ globals, no runtime allocation)
// ---------------------------------------------------------------------------
__device__ float g_Wn[DIN * PROJ_N];                 // repacked node weights [512][2048]
__device__ float g_Wp[DIN * PROJ_N];                 // repacked pos  weights
__device__ float g_PN[(size_t)ROWS * PROJ_N];        // node projections [16384][2048]
__device__ float g_PP[(size_t)ROWS * PROJ_N];        // pos  projections
__device__ float g_Hn[(size_t)ROWS * 1024];          // heads_node [16384][h*128+c]
__device__ float g_Hp[(size_t)ROWS * 1024];          // heads_pos

// ---------------------------------------------------------------------------
// Repack [H,D,64] per-head weights into one [D][2048] matrix:
//   cols [0,512)    : Q  (h*64+k)
//   cols [512,1024) : K
//   cols [1024,2048): V (2H heads)
// ---------------------------------------------------------------------------
__global__ void repack_kernel(const float* __restrict__ Wq,
                              const float* __restrict__ Wk,
                              const float* __restrict__ Wv,
                              float* __restrict__ Wcat) {
    int idx = blockIdx.x * blockDim.x + threadIdx.x;
    if (idx >= DIN * PROJ_N) return;
    int d = idx / PROJ_N;
    int j = idx % PROJ_N;
    float v;
    if (j < 512) {
        int h = j >> 6, k = j & 63;
        v = Wq[((size_t)(h * DIN + d)) * KDIM + k];
    } else if (j < 1024) {
        int jj = j - 512;
        int h = jj >> 6, k = jj & 63;
        v = Wk[((size_t)(h * DIN + d)) * KDIM + k];
    } else {
        int jj = j - 1024;
        int h = jj >> 6, k = jj & 63;                 // h in [0,16)
        v = Wv[((size_t)(h * DIN + d)) * KDIM + k];
    }
    Wcat[idx] = v;
}

// ---------------------------------------------------------------------------
// Generic SGEMM: C[M,N] = A[M,K] @ B[K,N], fp32, row-major.
// 128x128 block tile, K-step 8, 8x8 register tile, 256 threads.
// All dims here are multiples of 128 / 8, so no bounds checks.
// ---------------------------------------------------------------------------
__global__ __launch_bounds__(256)
void sgemm_kernel(const float* __restrict__ A, const float* __restrict__ B,
                  float* __restrict__ C, int M, int N, int K) {
    __shared__ float As[8][128];    // A tile, transposed: As[k][m]
    __shared__ float Bs[8][128];    // B tile: Bs[k][n]

    const int tid = threadIdx.x;
    const int bm = blockIdx.y << 7;
    const int bn = blockIdx.x << 7;
    const int tx = tid & 15;        // 16 thread cols
    const int ty = tid >> 4;        // 16 thread rows

    const int arow = tid >> 1;              // 0..127
    const int acol = (tid & 1) << 2;        // 0 or 4
    const int brow = tid >> 5;              // 0..7
    const int bcol = (tid & 31) << 2;       // 0..124

    float acc[8][8] = {};

    const float* Aptr = A + (size_t)(bm + arow) * K + acol;
    const float* Bptr = B + (size_t)brow * N + bn + bcol;

    for (int k0 = 0; k0 < K; k0 += 8) {
        float4 a4 = *(const float4*)(Aptr + k0);
        As[acol + 0][arow] = a4.x;
        As[acol + 1][arow] = a4.y;
        As[acol + 2][arow] = a4.z;
        As[acol + 3][arow] = a4.w;
        float4 b4 = *(const float4*)(Bptr + (size_t)k0 * N);
        *(float4*)&Bs[brow][bcol] = b4;
        __syncthreads();

#pragma unroll
        for (int kk = 0; kk < 8; kk++) {
            float ar[8], br[8];
#pragma unroll
            for (int i = 0; i < 8; i++) ar[i] = As[kk][(ty << 3) + i];
#pragma unroll
            for (int j = 0; j < 8; j++) br[j] = Bs[kk][(tx << 3) + j];
#pragma unroll
            for (int i = 0; i < 8; i++)
#pragma unroll
                for (int j = 0; j < 8; j++)
                    acc[i][j] += ar[i] * br[j];
        }
        __syncthreads();
    }

#pragma unroll
    for (int i = 0; i < 8; i++) {
        float* crow = C + (size_t)(bm + (ty << 3) + i) * N + bn + (tx << 3);
        float4 v0 = make_float4(acc[i][0], acc[i][1], acc[i][2], acc[i][3]);
        float4 v1 = make_float4(acc[i][4], acc[i][5], acc[i][6], acc[i][7]);
        *(float4*)(crow)     = v0;
        *(float4*)(crow + 4) = v1;
    }
}

// ---------------------------------------------------------------------------
// Fused flash-attention kernel.
// One block handles (head h, batch b, 64-row q-tile). It computes one softmax
// stream (attn1 or attn2) and accumulates TWO outputs: P@V_node_half and
// P@V_pos_half (the reference shares each attention across both value sets).
//
// Q/K/V come from the projection buffers [16384][2048]:
//   Q col = h*64, K col = 512 + h*64, V col = vbase + h*64.
// Outputs go to Hn/Hp [16384][1024] at col h*128 + ocol.
// Grid: (16 q-tiles, 16 batch, 8 heads), 256 threads, dynamic smem.
// ---------------------------------------------------------------------------
__global__ __launch_bounds__(256)
void attn_kernel(const float* __restrict__ Pq, const float* __restrict__ Pk,
                 const float* __restrict__ Va_, const float* __restrict__ Vb_,
                 float* __restrict__ HnO, float* __restrict__ HpO,
                 int vbase, int ocol) {
    extern __shared__ float sm[];
    float* Qt  = sm;                       // [64][68]  Qt[k][r]  (k-major, pre-scaled)
    float* Kt  = sm + 64 * ATTN_PAD;       // [64][68]  Kt[k][c]
    float* Vas = sm + 2 * 64 * ATTN_PAD;   // [64][68]  Vas[j][oc]
    float* Vbs = sm + 3 * 64 * ATTN_PAD;   // [64][68]
    float* Pt  = sm + 4 * 64 * ATTN_PAD;   // [64][68]  Pt[j][r]

    const int tid = threadIdx.x;
    const int qt = blockIdx.x, b = blockIdx.y, h = blockIdx.z;

    const size_t batch_off = (size_t)b * SEQ * PROJ_N;
    const float* qg  = Pq  + batch_off + (size_t)qt * 64 * PROJ_N + h * KDIM;
    const float* kg  = Pk  + batch_off + 512 + h * KDIM;
    const float* vag = Va_ + batch_off + vbase + h * KDIM;
    const float* vbg = Vb_ + batch_off + vbase + h * KDIM;

    const int lr = tid >> 4;              // 0..15 loader row
    const int lc = (tid & 15) << 2;       // 0..60 loader col (x4)

    // Load Q tile transposed into smem, pre-scaled by 1/sqrt(64)
#pragma unroll
    for (int i = 0; i < 4; i++) {
        int r = lr + (i << 4);
        float4 v = *(const float4*)(qg + (size_t)r * PROJ_N + lc);
        Qt[(lc + 0) * ATTN_PAD + r] = v.x * 0.125f;
        Qt[(lc + 1) * ATTN_PAD + r] = v.y * 0.125f;
        Qt[(lc + 2) * ATTN_PAD + r] = v.z * 0.125f;
        Qt[(lc + 3) * ATTN_PAD + r] = v.w * 0.125f;
    }

    const int tx = tid & 15, ty = tid >> 4;
    const int r0 = ty << 2, c0 = tx << 2;

    float Oa[4][4] = {}, Ob[4][4] = {};
    float m[4] = {-1e30f, -1e30f, -1e30f, -1e30f};
    float l[4] = {0.f, 0.f, 0.f, 0.f};

    for (int kt = 0; kt < 16; kt++) {
        // Load K (transposed) and both V tiles
#pragma unroll
        for (int i = 0; i < 4; i++) {
            int r = lr + (i << 4);
            size_t go = (size_t)(kt * 64 + r) * PROJ_N + lc;
            float4 kv = *(const float4*)(kg + go);
            Kt[(lc + 0) * ATTN_PAD + r] = kv.x;
            Kt[(lc + 1) * ATTN_PAD + r] = kv.y;
            Kt[(lc + 2) * ATTN_PAD + r] = kv.z;
            Kt[(lc + 3) * ATTN_PAD + r] = kv.w;
            float4 va = *(const float4*)(vag + go);
            *(float4*)&Vas[r * ATTN_PAD + lc] = va;
            float4 vb = *(const float4*)(vbg + go);
            *(float4*)&Vbs[r * ATTN_PAD + lc] = vb;
        }
        __syncthreads();

        // S tile: s[i][j] = sum_k Q[r0+i][k] * K[c0+j][k]  (Q pre-scaled)
        float s[4][4] = {};
#pragma unroll 8
        for (int k = 0; k < 64; k++) {
            float4 q4 = *(const float4*)&Qt[k * ATTN_PAD + r0];
            float4 k4 = *(const float4*)&Kt[k * ATTN_PAD + c0];
            float qv[4] = {q4.x, q4.y, q4.z, q4.w};
            float kv[4] = {k4.x, k4.y, k4.z, k4.w};
#pragma unroll
            for (int i = 0; i < 4; i++)
#pragma unroll
                for (int j = 0; j < 4; j++)
                    s[i][j] += qv[i] * kv[j];
        }

        // Online softmax per row (rows replicated across the 16 tx lanes)
#pragma unroll
        for (int i = 0; i < 4; i++) {
            float tmax = fmaxf(fmaxf(s[i][0], s[i][1]), fmaxf(s[i][2], s[i][3]));
            tmax = fmaxf(tmax, __shfl_xor_sync(0xffffffffu, tmax, 1));
            tmax = fmaxf(tmax, __shfl_xor_sync(0xffffffffu, tmax, 2));
            tmax = fmaxf(tmax, __shfl_xor_sync(0xffffffffu, tmax, 4));
            tmax = fmaxf(tmax, __shfl_xor_sync(0xffffffffu, tmax, 8));
            float mn = fmaxf(m[i], tmax);
            float sc = __expf(m[i] - mn);
            float ts = 0.f;
#pragma unroll
            for (int j = 0; j < 4; j++) {
                float p = __expf(s[i][j] - mn);
                s[i][j] = p;
                ts += p;
            }
            ts += __shfl_xor_sync(0xffffffffu, ts, 1);
            ts += __shfl_xor_sync(0xffffffffu, ts, 2);
            ts += __shfl_xor_sync(0xffffffffu, ts, 4);
            ts += __shfl_xor_sync(0xffffffffu, ts, 8);
            l[i] = l[i] * sc + ts;
            m[i] = mn;
#pragma unroll
            for (int j = 0; j < 4; j++) {
                Oa[i][j] *= sc;
                Ob[i][j] *= sc;
                Pt[(c0 + j) * ATTN_PAD + (r0 + i)] = s[i][j];
            }
        }
        __syncthreads();

        // O += P @ V (both value sets share P)
#pragma unroll 4
        for (int j = 0; j < 64; j++) {
            float4 p4  = *(const float4*)&Pt[j * ATTN_PAD + r0];
            float4 va4 = *(const float4*)&Vas[j * ATTN_PAD + c0];
            float4 vb4 = *(const float4*)&Vbs[j * ATTN_PAD + c0];
            float pv[4] = {p4.x, p4.y, p4.z, p4.w};
            float va[4] = {va4.x, va4.y, va4.z, va4.w};
            float vb[4] = {vb4.x, vb4.y, vb4.z, vb4.w};
#pragma unroll
            for (int i = 0; i < 4; i++)
#pragma unroll
                for (int jj = 0; jj < 4; jj++) {
                    Oa[i][jj] += pv[i] * va[jj];
                    Ob[i][jj] += pv[i] * vb[jj];
                }
        }
        __syncthreads();
    }

    // Epilogue: normalize and store
    const size_t orow0 = (size_t)(b * SEQ + qt * 64);
    const int colb = h * 128 + ocol + c0;
#pragma unroll
    for (int i = 0; i < 4; i++) {
        float inv = 1.0f / l[i];
        size_t off = (orow0 + r0 + i) * 1024 + colb;
        float4 oa = make_float4(Oa[i][0] * inv, Oa[i][1] * inv,
                                Oa[i][2] * inv, Oa[i][3] * inv);
        float4 ob = make_float4(Ob[i][0] * inv, Ob[i][1] * inv,
                                Ob[i][2] * inv, Ob[i][3] * inv);
        *(float4*)(HnO + off) = oa;
        *(float4*)(HpO + off) = ob;
    }
}

// ---------------------------------------------------------------------------
// Host launcher (graph-capturable: kernel launches only)
// ---------------------------------------------------------------------------
extern "C" void kernel_launch(void* const* d_in, const int* in_sizes, int n_in,
                              void* d_out, int out_size) {
    const float* Xn  = (const float*)d_in[0];
    const float* Xp  = (const float*)d_in[1];
    const float* Wqn = (const float*)d_in[2];
    const float* Wqp = (const float*)d_in[3];
    const float* Wkn = (const float*)d_in[4];
    const float* Wkp = (const float*)d_in[5];
    const float* Wvn = (const float*)d_in[6];
    const float* Wvp = (const float*)d_in[7];
    const float* Won = (const float*)d_in[8];
    const float* Wop = (const float*)d_in[9];
    float* out = (float*)d_out;

    float *Wn, *Wp, *PN, *PP, *Hn, *Hp;
    cudaGetSymbolAddress((void**)&Wn, g_Wn);
    cudaGetSymbolAddress((void**)&Wp, g_Wp);
    cudaGetSymbolAddress((void**)&PN, g_PN);
    cudaGetSymbolAddress((void**)&PP, g_PP);
    cudaGetSymbolAddress((void**)&Hn, g_Hn);
    cudaGetSymbolAddress((void**)&Hp, g_Hp);

    cudaFuncSetAttribute(attn_kernel,
                         cudaFuncAttributeMaxDynamicSharedMemorySize, ATTN_SMEM);

    // 1) Weight repack
    int rp_blocks = (DIN * PROJ_N + 255) / 256;
    repack_kernel<<<rp_blocks, 256>>>(Wqn, Wkn, Wvn, Wn);
    repack_kernel<<<rp_blocks, 256>>>(Wqp, Wkp, Wvp, Wp);

    // 2) Projections: [16384,512] @ [512,2048] per stream
    dim3 gproj(PROJ_N / 128, ROWS / 128);
    sgemm_kernel<<<gproj, 256>>>(Xn, Wn, PN, ROWS, PROJ_N, DIN);
    sgemm_kernel<<<gproj, 256>>>(Xp, Wp, PP, ROWS, PROJ_N, DIN);

    // 3) Attention
    //    attn1: Q/K from node projections, V halves = heads 0..7  (vbase 1024)
    //    attn2: Q/K from pos  projections, V halves = heads 8..15 (vbase 1536)
    dim3 ga(SEQ / 64, NB, NHEADS);
    attn_kernel<<<ga, 256, ATTN_SMEM>>>(PN, PN, PN, PP, Hn, Hp, 1024, 0);
    attn_kernel<<<ga, 256, ATTN_SMEM>>>(PP, PP, PN, PP, Hn, Hp, 1536, 64);

    // 4) Output projections (head-sum folded into K=1024 GEMM):
    //    out_node = Hn[16384,1024] @ W_out_node[1024,512], same for pos.
    dim3 gout(512 / 128, ROWS / 128);
    sgemm_kernel<<<gout, 256>>>(Hn, Won, out, ROWS, 512, 1024);
    sgemm_kernel<<<gout, 256>>>(Hp, Wop, out + (size_t)ROWS * 512, ROWS, 512, 1024);
}

// round 4
// speedup vs baseline: 2.0545x; 2.0545x over previous
#include <cuda_runtime.h>
#include <cuda_fp16.h>

// ===========================================================================
// B=16, N=1024, D=512, H=8, dk=64. ROWS=16384.
// HMMA (mma.sync m16n8k16) everywhere, fp32 accum, split-fp16 (hi+lo) operands
// for precision: A*B ~= Ahi*Bhi + Alo*Bhi + Ahi*Blo.
// ===========================================================================
#define ROWS 16384
#define PADK 72
#define TILEB (128 * PADK * 2)
#define GEMM_SMEM (4 * TILEB)

// ---------------------------------------------------------------------------
// Static device scratch (~1.25 GB)
// ---------------------------------------------------------------------------
__device__ __half g_WnTh [1024 * 512], g_WnTl [1024 * 512];
__device__ __half g_WpTh [1024 * 512], g_WpTl [1024 * 512];
__device__ __half g_WvnTh[1024 * 512], g_WvnTl[1024 * 512];
__device__ __half g_WvpTh[1024 * 512], g_WvpTl[1024 * 512];
__device__ __half g_WonTh[512 * 1024], g_WonTl[512 * 1024];
__device__ __half g_WopTh[512 * 1024], g_WopTl[512 * 1024];
__device__ __half g_Xnh[(size_t)ROWS * 512], g_Xnl[(size_t)ROWS * 512];
__device__ __half g_Xph[(size_t)ROWS * 512], g_Xpl[(size_t)ROWS * 512];
__device__ __half g_QKnh[(size_t)ROWS * 1024], g_QKnl[(size_t)ROWS * 1024];
__device__ __half g_QKph[(size_t)ROWS * 1024], g_QKpl[(size_t)ROWS * 1024];
__device__ __half g_Vth[(size_t)2048 * ROWS], g_Vtl[(size_t)2048 * ROWS];
__device__ float  g_S  [(size_t)128 * 1024 * 1024];
__device__ __half g_P  [(size_t)128 * 1024 * 1024];
__device__ __half g_Hnh[(size_t)ROWS * 1024], g_Hnl[(size_t)ROWS * 1024];
__device__ __half g_Hph[(size_t)ROWS * 1024], g_Hpl[(size_t)ROWS * 1024];

// ---------------------------------------------------------------------------
// PTX helpers
// ---------------------------------------------------------------------------
__device__ __forceinline__ unsigned smem_u32(const void* p) {
    unsigned a;
    asm("{ .reg .u64 t; cvta.to.shared.u64 t, %1; cvt.u32.u64 %0, t; }"
        : "=r"(a) : "l"(p));
    return a;
}
__device__ __forceinline__ void cpasync16(unsigned s, const void* g) {
    asm volatile("cp.async.cg.shared.global [%0], [%1], 16;" :: "r"(s), "l"(g));
}
__device__ __forceinline__ void cp_commit() {
    asm volatile("cp.async.commit_group;" ::: "memory");
}
__device__ __forceinline__ void cp_wait0() {
    asm volatile("cp.async.wait_group 0;" ::: "memory");
}
__device__ __forceinline__ void ldm4(unsigned& r0, unsigned& r1, unsigned& r2,
                                     unsigned& r3, unsigned a) {
    asm volatile("ldmatrix.sync.aligned.m8n8.x4.shared.b16 {%0,%1,%2,%3}, [%4];"
                 : "=r"(r0), "=r"(r1), "=r"(r2), "=r"(r3) : "r"(a));
}
__device__ __forceinline__ void mma16816(float* c, const unsigned* a,
                                         const unsigned* b) {
    asm volatile(
        "mma.sync.aligned.m16n8k16.row.col.f32.f16.f16.f32 "
        "{%0,%1,%2,%3}, {%4,%5,%6,%7}, {%8,%9}, {%0,%1,%2,%3};"
        : "+f"(c[0]), "+f"(c[1]), "+f"(c[2]), "+f"(c[3])
        : "r"(a[0]), "r"(a[1]), "r"(a[2]), "r"(a[3]), "r"(b[0]), "r"(b[1]));
}
__device__ __forceinline__ void split2(float v0, float v1, __half2& hi, __half2& lo) {
    __half h0 = __float2half_rn(v0), h1 = __float2half_rn(v1);
    __half l0 = __float2half_rn(v0 - __half2float(h0));
    __half l1 = __float2half_rn(v1 - __half2float(h1));
    hi = __halves2half2(h0, h1);
    lo = __halves2half2(l0, l1);
}

// ---------------------------------------------------------------------------
// Multi-term HMMA GEMM: C = sum_t At(M,K) * Bt(N,K)^T, fp16 in, fp32 accum.
// Block 128x128, BK=64, 512 threads (4x4 warps, 32x32 warp tiles).
// z decomposed h=z>>4, b=z&15.
// modes: 1 fp32 out (C0)
//        4 fp16 pair out (C0 hi, C1 lo)
//        5 fp16 pair out with V row remap orow=(r>>6)*128+(r&63)+halfoff
//        6 pair split by col: col<64 -> C0/C1 else C2/C3, col&63
// ---------------------------------------------------------------------------
__global__ __launch_bounds__(512)
void hgemm(const __half* __restrict__ A0, const __half* __restrict__ A1,
           const __half* __restrict__ A2,
           long long sAh, long long sAb, int lda,
           const __half* __restrict__ B0, const __half* __restrict__ B1,
           const __half* __restrict__ B2,
           long long sBh, long long sBb, int ldb,
           void* __restrict__ C0, void* __restrict__ C1,
           void* __restrict__ C2, void* __restrict__ C3,
           long long sCh, long long sCb, int ldc,
           int Kper, int nterm, int mode, int halfoff) {
    extern __shared__ __align__(16) char smem[];
    const unsigned smA = smem_u32(smem);
    const unsigned smB = smA + 2 * TILEB;

    const int tid = threadIdx.x;
    const int wid = tid >> 5, lane = tid & 31;
    const int wm = wid & 3, wn = wid >> 2;

    const int zh = (int)(blockIdx.z >> 4), zb = (int)(blockIdx.z & 15);

    // term base pointers (block-level, no thread offsets)
    const long long aoff = sAh * zh + sAb * zb + (long long)(blockIdx.y * 128) * lda;
    const long long boff = sBh * zh + sBb * zb + (long long)(blockIdx.x * 128) * ldb;
    const __half* At[3] = {A0 + aoff, A1 + aoff, A2 + aoff};
    const __half* Bt[3] = {B0 + boff, B1 + boff, B2 + boff};

    // loader thread offsets: rows r0c (0..63), r1c (64..127), 8x16B per row
    const int r0c = tid >> 3, s0c = tid & 7;
    const int r1c = r0c + 64;
    const int trA0 = r0c * lda + s0c * 8, trA1 = r1c * lda + s0c * 8;
    const int trB0 = r0c * ldb + s0c * 8, trB1 = r1c * ldb + s0c * 8;
    const unsigned so0 = (unsigned)(r0c * PADK + s0c * 8) * 2;
    const unsigned so1 = (unsigned)(r1c * PADK + s0c * 8) * 2;

    const int T = Kper >> 6;
    const int TT = nterm * T;

#define LOAD_TILE(g, bf)                                                      \
    do {                                                                      \
        int t_ = ((g) >= T) + ((g) >= 2 * T);                                 \
        int kk_ = (g) - t_ * T;                                               \
        const __half* ap = At[t_] + kk_ * 64;                                 \
        const __half* bp = Bt[t_] + kk_ * 64;                                 \
        cpasync16(smA + (bf) * TILEB + so0, ap + trA0);                       \
        cpasync16(smA + (bf) * TILEB + so1, ap + trA1);                       \
        cpasync16(smB + (bf) * TILEB + so0, bp + trB0);                       \
        cpasync16(smB + (bf) * TILEB + so1, bp + trB1);                       \
        cp_commit();                                                          \
    } while (0)

    LOAD_TILE(0, 0);

    float acc[2][4][4];
#pragma unroll
    for (int i = 0; i < 2; i++)
#pragma unroll
        for (int j = 0; j < 4; j++)
#pragma unroll
            for (int k = 0; k < 4; k++) acc[i][j][k] = 0.f;

    const int sub = lane >> 3, r8 = lane & 7;

    for (int g = 0; g < TT; g++) {
        const int bf = g & 1;
        cp_wait0();
        __syncthreads();
        if (g + 1 < TT) LOAD_TILE(g + 1, bf ^ 1);

        const unsigned ab = smA + bf * TILEB;
        const unsigned bb = smB + bf * TILEB;
#pragma unroll
        for (int ks = 0; ks < 4; ks++) {
            const int k0 = ks * 16;
            unsigned a[2][4];
#pragma unroll
            for (int mi = 0; mi < 2; mi++) {
                int mrow = wm * 32 + mi * 16 + r8 + (sub & 1) * 8;
                int mcol = k0 + (sub >> 1) * 8;
                ldm4(a[mi][0], a[mi][1], a[mi][2], a[mi][3],
                     ab + (unsigned)(mrow * PADK + mcol) * 2);
            }
            unsigned b[4][2];
#pragma unroll
            for (int np = 0; np < 2; np++) {
                int nrow = wn * 32 + np * 16 + r8 + (sub >> 1) * 8;
                int kcol = k0 + (sub & 1) * 8;
                unsigned q0, q1, q2, q3;
                ldm4(q0, q1, q2, q3, bb + (unsigned)(nrow * PADK + kcol) * 2);
                b[np * 2][0] = q0; b[np * 2][1] = q1;
                b[np * 2 + 1][0] = q2; b[np * 2 + 1][1] = q3;
            }
#pragma unroll
            for (int mi = 0; mi < 2; mi++)
#pragma unroll
                for (int ni = 0; ni < 4; ni++)
                    mma16816(acc[mi][ni], a[mi], b[ni]);
        }
        __syncthreads();
    }
#undef LOAD_TILE

    // ---- epilogue ----
    const int trow = lane >> 2, tcol = (lane & 3) * 2;
    const long long coff = sCh * zh + sCb * zb;

#pragma unroll
    for (int mi = 0; mi < 2; mi++) {
#pragma unroll
        for (int ni = 0; ni < 4; ni++) {
            int rg = blockIdx.y * 128 + wm * 32 + mi * 16 + trow;
            int cg = blockIdx.x * 128 + wn * 32 + ni * 8 + tcol;
            float* ac = acc[mi][ni];
            if (mode == 1) {
                float* p0 = (float*)C0 + coff + (size_t)rg * ldc + cg;
                float* p1 = (float*)C0 + coff + (size_t)(rg + 8) * ldc + cg;
                *(float2*)p0 = make_float2(ac[0], ac[1]);
                *(float2*)p1 = make_float2(ac[2], ac[3]);
            } else if (mode == 4) {
                __half2 h, l;
                size_t o0 = coff + (size_t)rg * ldc + cg;
                size_t o1 = coff + (size_t)(rg + 8) * ldc + cg;
                split2(ac[0], ac[1], h, l);
                *(__half2*)((__half*)C0 + o0) = h;
                *(__half2*)((__half*)C1 + o0) = l;
                split2(ac[2], ac[3], h, l);
                *(__half2*)((__half*)C0 + o1) = h;
                *(__half2*)((__half*)C1 + o1) = l;
            } else if (mode == 5) {
                int ra = ((rg >> 6) << 7) + (rg & 63) + halfoff;
                int rb0 = rg + 8;
                int rb = ((rb0 >> 6) << 7) + (rb0 & 63) + halfoff;
                __half2 h, l;
                size_t o0 = coff + (size_t)ra * ldc + cg;
                size_t o1 = coff + (size_t)rb * ldc + cg;
                split2(ac[0], ac[1], h, l);
                *(__half2*)((__half*)C0 + o0) = h;
                *(__half2*)((__half*)C1 + o0) = l;
                split2(ac[2], ac[3], h, l);
                *(__half2*)((__half*)C0 + o1) = h;
                *(__half2*)((__half*)C1 + o1) = l;
            } else {  // mode 6
                __half* hA = (cg < 64) ? (__half*)C0 : (__half*)C2;
                __half* lA = (cg < 64) ? (__half*)C1 : (__half*)C3;
                int cl = cg & 63;
                size_t o0 = coff + (size_t)rg * ldc + cl;
                size_t o1 = coff + (size_t)(rg + 8) * ldc + cl;
                __half2 h, l;
                split2(ac[0], ac[1], h, l);
                *(__half2*)(hA + o0) = h;
                *(__half2*)(lA + o0) = l;
                split2(ac[2], ac[3], h, l);
                *(__half2*)(hA + o1) = h;
                *(__half2*)(lA + o1) = l;
            }
        }
    }
}

// ---------------------------------------------------------------------------
// Prep kernels (pair outputs)
// ---------------------------------------------------------------------------
__global__ void cvt_pair(const float* __restrict__ X, __half* __restrict__ Yh,
                         __half* __restrict__ Yl, int n4) {
    int i = blockIdx.x * blockDim.x + threadIdx.x;
    if (i >= n4) return;
    float4 v = ((const float4*)X)[i];
    __half2 h0, l0, h1, l1;
    split2(v.x, v.y, h0, l0);
    split2(v.z, v.w, h1, l1);
    uint2 uh, ul;
    uh.x = *reinterpret_cast<unsigned*>(&h0);
    uh.y = *reinterpret_cast<unsigned*>(&h1);
    ul.x = *reinterpret_cast<unsigned*>(&l0);
    ul.y = *reinterpret_cast<unsigned*>(&l1);
    ((uint2*)Yh)[i] = uh;
    ((uint2*)Yl)[i] = ul;
}

__global__ void repack_qk(const float* __restrict__ Wq, const float* __restrict__ Wk,
                          __half* __restrict__ WTh, __half* __restrict__ WTl) {
    int idx = blockIdx.x * blockDim.x + threadIdx.x;
    if (idx >= 1024 * 512) return;
    int j = idx >> 9, d = idx & 511;
    int jj = j & 511;
    float v;
    if (j < 512)
        v = Wq[((size_t)((jj >> 6) * 512 + d)) * 64 + (jj & 63)] * 0.125f;
    else
        v = Wk[((size_t)((jj >> 6) * 512 + d)) * 64 + (jj & 63)];
    __half h = __float2half_rn(v);
    WTh[idx] = h;
    WTl[idx] = __float2half_rn(v - __half2float(h));
}

__global__ void repack_v(const float* __restrict__ Wv, __half* __restrict__ WTh,
                         __half* __restrict__ WTl) {
    int idx = blockIdx.x * blockDim.x + threadIdx.x;
    if (idx >= 1024 * 512) return;
    int j = idx >> 9, d = idx & 511;
    float v = Wv[((size_t)((j >> 6) * 512 + d)) * 64 + (j & 63)];
    __half h = __float2half_rn(v);
    WTh[idx] = h;
    WTl[idx] = __float2half_rn(v - __half2float(h));
}

__global__ void repack_wo(const float* __restrict__ Wo, __half* __restrict__ WTh,
                          __half* __restrict__ WTl) {
    int idx = blockIdx.x * blockDim.x + threadIdx.x;
    if (idx >= 512 * 1024) return;
    int e = idx >> 10, j = idx & 1023;
    float v = Wo[(size_t)j * 512 + e];
    __half h = __float2half_rn(v);
    WTh[idx] = h;
    WTl[idx] = __float2half_rn(v - __half2float(h));
}

// ---------------------------------------------------------------------------
// Row softmax over 1024 (scores pre-scaled by 1/8), fp32 in -> fp16 out
// ---------------------------------------------------------------------------
__global__ __launch_bounds__(256)
void softmax_k(const float* __restrict__ S, __half* __restrict__ P) {
    __shared__ float red[8];
    const size_t row = blockIdx.x;
    const int t = threadIdx.x;
    float4 v = ((const float4*)(S + (row << 10)))[t];

    float m = fmaxf(fmaxf(v.x, v.y), fmaxf(v.z, v.w));
#pragma unroll
    for (int o = 16; o; o >>= 1) m = fmaxf(m, __shfl_xor_sync(~0u, m, o));
    if ((t & 31) == 0) red[t >> 5] = m;
    __syncthreads();
    if (t < 32) {
        float mm = (t < 8) ? red[t] : -1e30f;
#pragma unroll
        for (int o = 4; o; o >>= 1) mm = fmaxf(mm, __shfl_xor_sync(~0u, mm, o));
        if (t == 0) red[0] = mm;
    }
    __syncthreads();
    m = red[0];
    __syncthreads();

    float e0 = __expf(v.x - m), e1 = __expf(v.y - m);
    float e2 = __expf(v.z - m), e3 = __expf(v.w - m);
    float s = e0 + e1 + e2 + e3;
#pragma unroll
    for (int o = 16; o; o >>= 1) s += __shfl_xor_sync(~0u, s, o);
    if ((t & 31) == 0) red[t >> 5] = s;
    __syncthreads();
    if (t < 32) {
        float ss = (t < 8) ? red[t] : 0.f;
#pragma unroll
        for (int o = 4; o; o >>= 1) ss += __shfl_xor_sync(~0u, ss, o);
        if (t == 0) red[0] = ss;
    }
    __syncthreads();
    float inv = 1.0f / red[0];

    __half2 a = __floats2half2_rn(e0 * inv, e1 * inv);
    __half2 b = __floats2half2_rn(e2 * inv, e3 * inv);
    uint2 w;
    w.x = *reinterpret_cast<unsigned*>(&a);
    w.y = *reinterpret_cast<unsigned*>(&b);
    ((uint2*)(P + (row << 10)))[t] = w;
}

// ---------------------------------------------------------------------------
// Host launcher
// ---------------------------------------------------------------------------
extern "C" void kernel_launch(void* const* d_in, const int* in_sizes, int n_in,
                              void* d_out, int out_size) {
    const float* Xn  = (const float*)d_in[0];
    const float* Xp  = (const float*)d_in[1];
    const float* Wqn = (const float*)d_in[2];
    const float* Wqp = (const float*)d_in[3];
    const float* Wkn = (const float*)d_in[4];
    const float* Wkp = (const float*)d_in[5];
    const float* Wvn = (const float*)d_in[6];
    const float* Wvp = (const float*)d_in[7];
    const float* Won = (const float*)d_in[8];
    const float* Wop = (const float*)d_in[9];
    float* out = (float*)d_out;

    __half *WnTh, *WnTl, *WpTh, *WpTl, *WvnTh, *WvnTl, *WvpTh, *WvpTl;
    __half *WonTh, *WonTl, *WopTh, *WopTl;
    __half *Xnh, *Xnl, *Xph, *Xpl, *QKnh, *QKnl, *QKph, *QKpl;
    __half *Vth, *Vtl, *P, *Hnh, *Hnl, *Hph, *Hpl;
    float* S;
    cudaGetSymbolAddress((void**)&WnTh,  g_WnTh);
    cudaGetSymbolAddress((void**)&WnTl,  g_WnTl);
    cudaGetSymbolAddress((void**)&WpTh,  g_WpTh);
    cudaGetSymbolAddress((void**)&WpTl,  g_WpTl);
    cudaGetSymbolAddress((void**)&WvnTh, g_WvnTh);
    cudaGetSymbolAddress((void**)&WvnTl, g_WvnTl);
    cudaGetSymbolAddress((void**)&WvpTh, g_WvpTh);
    cudaGetSymbolAddress((void**)&WvpTl, g_WvpTl);
    cudaGetSymbolAddress((void**)&WonTh, g_WonTh);
    cudaGetSymbolAddress((void**)&WonTl, g_WonTl);
    cudaGetSymbolAddress((void**)&WopTh, g_WopTh);
    cudaGetSymbolAddress((void**)&WopTl, g_WopTl);
    cudaGetSymbolAddress((void**)&Xnh,   g_Xnh);
    cudaGetSymbolAddress((void**)&Xnl,   g_Xnl);
    cudaGetSymbolAddress((void**)&Xph,   g_Xph);
    cudaGetSymbolAddress((void**)&Xpl,   g_Xpl);
    cudaGetSymbolAddress((void**)&QKnh,  g_QKnh);
    cudaGetSymbolAddress((void**)&QKnl,  g_QKnl);
    cudaGetSymbolAddress((void**)&QKph,  g_QKph);
    cudaGetSymbolAddress((void**)&QKpl,  g_QKpl);
    cudaGetSymbolAddress((void**)&Vth,   g_Vth);
    cudaGetSymbolAddress((void**)&Vtl,   g_Vtl);
    cudaGetSymbolAddress((void**)&S,     g_S);
    cudaGetSymbolAddress((void**)&P,     g_P);
    cudaGetSymbolAddress((void**)&Hnh,   g_Hnh);
    cudaGetSymbolAddress((void**)&Hnl,   g_Hnl);
    cudaGetSymbolAddress((void**)&Hph,   g_Hph);
    cudaGetSymbolAddress((void**)&Hpl,   g_Hpl);

    cudaFuncSetAttribute(hgemm, cudaFuncAttributeMaxDynamicSharedMemorySize,
                         GEMM_SMEM);

    // 1) repacks + conversions (pair)
    repack_qk<<<2048, 256>>>(Wqn, Wkn, WnTh, WnTl);
    repack_qk<<<2048, 256>>>(Wqp, Wkp, WpTh, WpTl);
    repack_v <<<2048, 256>>>(Wvn, WvnTh, WvnTl);
    repack_v <<<2048, 256>>>(Wvp, WvpTh, WvpTl);
    repack_wo<<<2048, 256>>>(Won, WonTh, WonTl);
    repack_wo<<<2048, 256>>>(Wop, WopTh, WopTl);
    cvt_pair<<<8192, 256>>>(Xn, Xnh, Xnl, ROWS * 512 / 4);
    cvt_pair<<<8192, 256>>>(Xp, Xph, Xpl, ROWS * 512 / 4);

    // 2) Q,K projections, 3-term, pair out: QK[16384,1024]
    hgemm<<<dim3(8, 128, 1), 512, GEMM_SMEM>>>(
        Xnh, Xnl, Xnh, 0, 0, 512,
        WnTh, WnTh, WnTl, 0, 0, 512,
        QKnh, QKnl, nullptr, nullptr, 0, 0, 1024, 512, 3, 4, 0);
    hgemm<<<dim3(8, 128, 1), 512, GEMM_SMEM>>>(
        Xph, Xpl, Xph, 0, 0, 512,
        WpTh, WpTh, WpTl, 0, 0, 512,
        QKph, QKpl, nullptr, nullptr, 0, 0, 1024, 512, 3, 4, 0);

    // 3) V transposed, 3-term, pair out with row remap:
    //    Vt[(s*8+h)*128 + half*64 + c][token]
    hgemm<<<dim3(128, 8, 1), 512, GEMM_SMEM>>>(
        WvnTh, WvnTl, WvnTh, 0, 0, 512,
        Xnh, Xnh, Xnl, 0, 0, 512,
        Vth, Vtl, nullptr, nullptr, 0, 0, ROWS, 512, 3, 5, 0);
    hgemm<<<dim3(128, 8, 1), 512, GEMM_SMEM>>>(
        WvpTh, WvpTl, WvpTh, 0, 0, 512,
        Xph, Xph, Xpl, 0, 0, 512,
        Vth, Vtl, nullptr, nullptr, 0, 0, ROWS, 512, 3, 5, 64);

    // 4) attention per softmax stream
    for (int s = 0; s < 2; s++) {
        const __half* Qh = s ? QKph : QKnh;
        const __half* Ql = s ? QKpl : QKnl;
        // S = Qhi*Khi + Qlo*Khi + Qhi*Klo, fp32 out
        hgemm<<<dim3(8, 8, 128), 512, GEMM_SMEM>>>(
            Qh, Ql, Qh, 64, 1048576, 1024,
            Qh + 512, Qh + 512, Ql + 512, 64, 1048576, 1024,
            S, nullptr, nullptr, nullptr, 16777216, 1048576, 1024,
            64, 3, 1, 0);
        softmax_k<<<131072, 256>>>(S, P);
        // O = P*Vhi + P*Vlo ; split-col pair epilogue -> Hn/Hp hi,lo
        hgemm<<<dim3(1, 8, 128), 512, GEMM_SMEM>>>(
            P, P, nullptr, 16777216, 1048576, 1024,
            Vth + (size_t)s * 16777216, Vtl + (size_t)s * 16777216, nullptr,
            2097152, 1024, ROWS,
            Hnh + s * 64, Hnl + s * 64, Hph + s * 64, Hpl + s * 64,
            128, 1048576, 1024, 1024, 2, 6, 0);
    }

    // 5) output projections, 3-term, fp32 out
    hgemm<<<dim3(4, 128, 1), 512, GEMM_SMEM>>>(
        Hnh, Hnl, Hnh, 0, 0, 1024,
        WonTh, WonTh, WonTl, 0, 0, 1024,
        out, nullptr, nullptr, nullptr, 0, 0, 512, 1024, 3, 1, 0);
    hgemm<<<dim3(4, 128, 1), 512, GEMM_SMEM>>>(
        Hph, Hpl, Hph, 0, 0, 1024,
        WopTh, WopTh, WopTl, 0, 0, 1024,
        out + (size_t)ROWS * 512, nullptr, nullptr, nullptr, 0, 0, 512,
        1024, 3, 1, 0);
}

// round 5
// speedup vs baseline: 3.1355x; 1.5261x over previous
#include <cuda_runtime.h>
#include <cuda_fp16.h>

// ===========================================================================
// B=16, N=1024, D=512, H=8, dk=64. ROWS=16384.
// HMMA (mma.sync m16n8k16) everywhere, fp32 accum, split-fp16 (hi+lo) operands
// for precision. Attention is a fused flash kernel (S 3-term, online softmax,
// PV with V-hi only).
// ===========================================================================
#define ROWS 16384
#define PADK 72
#define TILEB (128 * PADK * 2)
#define GEMM_SMEM (4 * TILEB)

// Fused attention smem layout (bytes)
#define NKT   16
#define OFF_Q  0                    // Qhi 18432 + Qlo 18432
#define OFF_KV 36864                // 2 bufs x (Khi 9216 | Klo 9216 | V 18432)
#define KVBUF  36864
#define OFF_S  110592               // 128*66*4 fp32
#define OFF_P  144384               // 128*72*2 fp16
#define OFF_M  162816               // 128 fp32 row-max
#define OFF_L  163328               // 128 fp32 row-sum
#define OFF_F  163840               // 128 fp32 rescale
#define FA_SMEM 164352

// ---------------------------------------------------------------------------
// Static device scratch
// ---------------------------------------------------------------------------
__device__ __half g_WnTh [1024 * 512], g_WnTl [1024 * 512];
__device__ __half g_WpTh [1024 * 512], g_WpTl [1024 * 512];
__device__ __half g_WvnTh[1024 * 512], g_WvnTl[1024 * 512];
__device__ __half g_WvpTh[1024 * 512], g_WvpTl[1024 * 512];
__device__ __half g_WonTh[512 * 1024], g_WonTl[512 * 1024];
__device__ __half g_WopTh[512 * 1024], g_WopTl[512 * 1024];
__device__ __half g_Xnh[(size_t)ROWS * 512], g_Xnl[(size_t)ROWS * 512];
__device__ __half g_Xph[(size_t)ROWS * 512], g_Xpl[(size_t)ROWS * 512];
__device__ __half g_QKnh[(size_t)ROWS * 1024], g_QKnl[(size_t)ROWS * 1024];
__device__ __half g_QKph[(size_t)ROWS * 1024], g_QKpl[(size_t)ROWS * 1024];
__device__ __half g_Vth[(size_t)2048 * ROWS], g_Vtl[(size_t)2048 * ROWS];
__device__ __half g_Hnh[(size_t)ROWS * 1024], g_Hnl[(size_t)ROWS * 1024];
__device__ __half g_Hph[(size_t)ROWS * 1024], g_Hpl[(size_t)ROWS * 1024];

// ---------------------------------------------------------------------------
// PTX helpers
// ---------------------------------------------------------------------------
__device__ __forceinline__ unsigned smem_u32(const void* p) {
    unsigned a;
    asm("{ .reg .u64 t; cvta.to.shared.u64 t, %1; cvt.u32.u64 %0, t; }"
        : "=r"(a) : "l"(p));
    return a;
}
__device__ __forceinline__ void cpasync16(unsigned s, const void* g) {
    asm volatile("cp.async.cg.shared.global [%0], [%1], 16;" :: "r"(s), "l"(g));
}
__device__ __forceinline__ void cp_commit() {
    asm volatile("cp.async.commit_group;" ::: "memory");
}
__device__ __forceinline__ void cp_wait0() {
    asm volatile("cp.async.wait_group 0;" ::: "memory");
}
__device__ __forceinline__ void ldm4(unsigned& r0, unsigned& r1, unsigned& r2,
                                     unsigned& r3, unsigned a) {
    asm volatile("ldmatrix.sync.aligned.m8n8.x4.shared.b16 {%0,%1,%2,%3}, [%4];"
                 : "=r"(r0), "=r"(r1), "=r"(r2), "=r"(r3) : "r"(a));
}
__device__ __forceinline__ void mma16816(float* c, const unsigned* a,
                                         const unsigned* b) {
    asm volatile(
        "mma.sync.aligned.m16n8k16.row.col.f32.f16.f16.f32 "
        "{%0,%1,%2,%3}, {%4,%5,%6,%7}, {%8,%9}, {%0,%1,%2,%3};"
        : "+f"(c[0]), "+f"(c[1]), "+f"(c[2]), "+f"(c[3])
        : "r"(a[0]), "r"(a[1]), "r"(a[2]), "r"(a[3]), "r"(b[0]), "r"(b[1]));
}
__device__ __forceinline__ void split2(float v0, float v1, __half2& hi, __half2& lo) {
    __half h0 = __float2half_rn(v0), h1 = __float2half_rn(v1);
    __half l0 = __float2half_rn(v0 - __half2float(h0));
    __half l1 = __float2half_rn(v1 - __half2float(h1));
    hi = __halves2half2(h0, h1);
    lo = __halves2half2(l0, l1);
}

// ---------------------------------------------------------------------------
// Multi-term HMMA GEMM (unchanged from R4): C = sum_t At(M,K)*Bt(N,K)^T.
// modes: 1 fp32 out | 4 fp16 pair out | 5 pair out + V row remap
// ---------------------------------------------------------------------------
__global__ __launch_bounds__(512)
void hgemm(const __half* __restrict__ A0, const __half* __restrict__ A1,
           const __half* __restrict__ A2,
           long long sAh, long long sAb, int lda,
           const __half* __restrict__ B0, const __half* __restrict__ B1,
           const __half* __restrict__ B2,
           long long sBh, long long sBb, int ldb,
           void* __restrict__ C0, void* __restrict__ C1,
           long long sCh, long long sCb, int ldc,
           int Kper, int nterm, int mode, int halfoff) {
    extern __shared__ __align__(16) char smem[];
    const unsigned smA = smem_u32(smem);
    const unsigned smB = smA + 2 * TILEB;

    const int tid = threadIdx.x;
    const int wid = tid >> 5, lane = tid & 31;
    const int wm = wid & 3, wn = wid >> 2;

    const int zh = (int)(blockIdx.z >> 4), zb = (int)(blockIdx.z & 15);
    const long long aoff = sAh * zh + sAb * zb + (long long)(blockIdx.y * 128) * lda;
    const long long boff = sBh * zh + sBb * zb + (long long)(blockIdx.x * 128) * ldb;
    const __half* At[3] = {A0 + aoff, A1 + aoff, A2 + aoff};
    const __half* Bt[3] = {B0 + boff, B1 + boff, B2 + boff};

    const int r0c = tid >> 3, s0c = tid & 7;
    const int r1c = r0c + 64;
    const int trA0 = r0c * lda + s0c * 8, trA1 = r1c * lda + s0c * 8;
    const int trB0 = r0c * ldb + s0c * 8, trB1 = r1c * ldb + s0c * 8;
    const unsigned so0 = (unsigned)(r0c * PADK + s0c * 8) * 2;
    const unsigned so1 = (unsigned)(r1c * PADK + s0c * 8) * 2;

    const int T = Kper >> 6;
    const int TT = nterm * T;

#define LOAD_TILE(g, bf)                                                      \
    do {                                                                      \
        int t_ = ((g) >= T) + ((g) >= 2 * T);                                 \
        int kk_ = (g) - t_ * T;                                               \
        const __half* ap = At[t_] + kk_ * 64;                                 \
        const __half* bp = Bt[t_] + kk_ * 64;                                 \
        cpasync16(smA + (bf) * TILEB + so0, ap + trA0);                       \
        cpasync16(smA + (bf) * TILEB + so1, ap + trA1);                       \
        cpasync16(smB + (bf) * TILEB + so0, bp + trB0);                       \
        cpasync16(smB + (bf) * TILEB + so1, bp + trB1);                       \
        cp_commit();                                                          \
    } while (0)

    LOAD_TILE(0, 0);

    float acc[2][4][4];
#pragma unroll
    for (int i = 0; i < 2; i++)
#pragma unroll
        for (int j = 0; j < 4; j++)
#pragma unroll
            for (int k = 0; k < 4; k++) acc[i][j][k] = 0.f;

    const int sub = lane >> 3, r8 = lane & 7;

    for (int g = 0; g < TT; g++) {
        const int bf = g & 1;
        cp_wait0();
        __syncthreads();
        if (g + 1 < TT) LOAD_TILE(g + 1, bf ^ 1);

        const unsigned ab = smA + bf * TILEB;
        const unsigned bb = smB + bf * TILEB;
#pragma unroll
        for (int ks = 0; ks < 4; ks++) {
            const int k0 = ks * 16;
            unsigned a[2][4];
#pragma unroll
            for (int mi = 0; mi < 2; mi++) {
                int mrow = wm * 32 + mi * 16 + r8 + (sub & 1) * 8;
                int mcol = k0 + (sub >> 1) * 8;
                ldm4(a[mi][0], a[mi][1], a[mi][2], a[mi][3],
                     ab + (unsigned)(mrow * PADK + mcol) * 2);
            }
            unsigned b[4][2];
#pragma unroll
            for (int np = 0; np < 2; np++) {
                int nrow = wn * 32 + np * 16 + r8 + (sub >> 1) * 8;
                int kcol = k0 + (sub & 1) * 8;
                unsigned q0, q1, q2, q3;
                ldm4(q0, q1, q2, q3, bb + (unsigned)(nrow * PADK + kcol) * 2);
                b[np * 2][0] = q0; b[np * 2][1] = q1;
                b[np * 2 + 1][0] = q2; b[np * 2 + 1][1] = q3;
            }
#pragma unroll
            for (int mi = 0; mi < 2; mi++)
#pragma unroll
                for (int ni = 0; ni < 4; ni++)
                    mma16816(acc[mi][ni], a[mi], b[ni]);
        }
        __syncthreads();
    }
#undef LOAD_TILE

    const int trow = lane >> 2, tcol = (lane & 3) * 2;
    const long long coff = sCh * zh + sCb * zb;

#pragma unroll
    for (int mi = 0; mi < 2; mi++) {
#pragma unroll
        for (int ni = 0; ni < 4; ni++) {
            int rg = blockIdx.y * 128 + wm * 32 + mi * 16 + trow;
            int cg = blockIdx.x * 128 + wn * 32 + ni * 8 + tcol;
            float* ac = acc[mi][ni];
            if (mode == 1) {
                float* p0 = (float*)C0 + coff + (size_t)rg * ldc + cg;
                float* p1 = (float*)C0 + coff + (size_t)(rg + 8) * ldc + cg;
                *(float2*)p0 = make_float2(ac[0], ac[1]);
                *(float2*)p1 = make_float2(ac[2], ac[3]);
            } else if (mode == 4) {
                __half2 h, l;
                size_t o0 = coff + (size_t)rg * ldc + cg;
                size_t o1 = coff + (size_t)(rg + 8) * ldc + cg;
                split2(ac[0], ac[1], h, l);
                *(__half2*)((__half*)C0 + o0) = h;
                *(__half2*)((__half*)C1 + o0) = l;
                split2(ac[2], ac[3], h, l);
                *(__half2*)((__half*)C0 + o1) = h;
                *(__half2*)((__half*)C1 + o1) = l;
            } else {  // mode 5: pair + V row remap
                int ra = ((rg >> 6) << 7) + (rg & 63) + halfoff;
                int rb0 = rg + 8;
                int rb = ((rb0 >> 6) << 7) + (rb0 & 63) + halfoff;
                __half2 h, l;
                size_t o0 = coff + (size_t)ra * ldc + cg;
                size_t o1 = coff + (size_t)rb * ldc + cg;
                split2(ac[0], ac[1], h, l);
                *(__half2*)((__half*)C0 + o0) = h;
                *(__half2*)((__half*)C1 + o0) = l;
                split2(ac[2], ac[3], h, l);
                *(__half2*)((__half*)C0 + o1) = h;
                *(__half2*)((__half*)C1 + o1) = l;
            }
        }
    }
}

// ---------------------------------------------------------------------------
// Fused flash attention. Block = 128 q-rows for one (stream, h, b).
// S = Qhi*Khi^T + Qlo*Khi^T + Qhi*Klo^T (Q pre-scaled by 1/8), online softmax,
// O += P * Vhi^T. Epilogue: pair-split writes into Hn/Hp (hi,lo).
// Grid (8 qtiles, 128 z=h*16+b), 512 threads.
// ---------------------------------------------------------------------------
__global__ __launch_bounds__(512)
void flash_attn(const __half* __restrict__ QKh, const __half* __restrict__ QKl,
                const __half* __restrict__ Vh,
                __half* __restrict__ C0, __half* __restrict__ C1,
                __half* __restrict__ C2, __half* __restrict__ C3) {
    extern __shared__ __align__(16) char smem[];
    const unsigned sb = smem_u32(smem);
    float* Sf  = (float*)(smem + OFF_S);
    __half* Pm = (__half*)(smem + OFF_P);
    float* smM = (float*)(smem + OFF_M);
    float* smL = (float*)(smem + OFF_L);
    float* smF = (float*)(smem + OFF_F);

    const int tid = threadIdx.x, wid = tid >> 5, lane = tid & 31;
    const int wm = wid & 3, wn = wid >> 2;
    const int sub = lane >> 3, r8 = lane & 7;
    const int trow = lane >> 2, tcol = (lane & 3) * 2;
    const int qt = blockIdx.x, z = blockIdx.y;
    const int h = z >> 4, b = z & 15;

    if (tid < 128) { smM[tid] = -1e30f; smL[tid] = 0.f; }

    // Q tile load (hi + lo), 128x64 @ stride 72
    {
        const size_t rbase = (size_t)(b << 10) + qt * 128;
        int c0 = tid, c1 = tid + 512;
        int r0 = c0 >> 3, s0 = c0 & 7, r1 = c1 >> 3, s1 = c1 & 7;
        int col0 = h * 64 + s0 * 8, col1 = h * 64 + s1 * 8;
        cpasync16(sb + OFF_Q + (unsigned)(r0 * 72 + s0 * 8) * 2,
                  QKh + (rbase + r0) * 1024 + col0);
        cpasync16(sb + OFF_Q + (unsigned)(r1 * 72 + s1 * 8) * 2,
                  QKh + (rbase + r1) * 1024 + col1);
        cpasync16(sb + OFF_Q + 18432 + (unsigned)(r0 * 72 + s0 * 8) * 2,
                  QKl + (rbase + r0) * 1024 + col0);
        cpasync16(sb + OFF_Q + 18432 + (unsigned)(r1 * 72 + s1 * 8) * 2,
                  QKl + (rbase + r1) * 1024 + col1);
    }

#define LOAD_KV(kt, bi)                                                       \
    do {                                                                      \
        int rr = tid >> 3, ss = tid & 7;                                      \
        size_t gr = (size_t)(b << 10) + (kt) * 64 + rr;                       \
        unsigned sof = (unsigned)(rr * 72 + ss * 8) * 2;                      \
        cpasync16(sb + OFF_KV + (bi) * KVBUF + sof,                           \
                  QKh + gr * 1024 + 512 + h * 64 + ss * 8);                   \
        cpasync16(sb + OFF_KV + (bi) * KVBUF + 9216 + sof,                    \
                  QKl + gr * 1024 + 512 + h * 64 + ss * 8);                   \
        int v0 = tid, v1 = tid + 512;                                         \
        int vr0 = v0 >> 3, vs0 = v0 & 7, vr1 = v1 >> 3, vs1 = v1 & 7;         \
        size_t vcb = (size_t)(b << 10) + (kt) * 64;                           \
        cpasync16(sb + OFF_KV + (bi) * KVBUF + 18432 +                        \
                      (unsigned)(vr0 * 72 + vs0 * 8) * 2,                     \
                  Vh + (size_t)(h * 128 + vr0) * 16384 + vcb + vs0 * 8);      \
        cpasync16(sb + OFF_KV + (bi) * KVBUF + 18432 +                        \
                      (unsigned)(vr1 * 72 + vs1 * 8) * 2,                     \
                  Vh + (size_t)(h * 128 + vr1) * 16384 + vcb + vs1 * 8);      \
        cp_commit();                                                          \
    } while (0)

    LOAD_KV(0, 0);   // commit covers Q loads too
    cp_wait0();

    float O[2][4][4] = {};

    for (int kt = 0; kt < NKT; kt++) {
        const int bi = kt & 1;
        if (kt) cp_wait0();
        __syncthreads();
        if (kt + 1 < NKT) LOAD_KV(kt + 1, bi ^ 1);

        const unsigned Kh = sb + OFF_KV + bi * KVBUF;
        const unsigned Kl = Kh + 9216;
        const unsigned Vb = Kh + 18432;

        // ---- S phase: warp tile 32(m) x 16(n keys), 3 terms ----
        float acc[2][2][4] = {};
#pragma unroll
        for (int ks = 0; ks < 4; ks++) {
            const int k0 = ks * 16;
            unsigned ah[2][4], al[2][4];
#pragma unroll
            for (int mi = 0; mi < 2; mi++) {
                unsigned off = (unsigned)((wm * 32 + mi * 16 + r8 + (sub & 1) * 8) * 72 +
                                          k0 + (sub >> 1) * 8) * 2;
                ldm4(ah[mi][0], ah[mi][1], ah[mi][2], ah[mi][3], sb + OFF_Q + off);
                ldm4(al[mi][0], al[mi][1], al[mi][2], al[mi][3],
                     sb + OFF_Q + 18432 + off);
            }
            unsigned bh[2][2], bl[2][2];
            {
                unsigned off = (unsigned)((wn * 16 + r8 + (sub >> 1) * 8) * 72 +
                                          k0 + (sub & 1) * 8) * 2;
                unsigned q0, q1, q2, q3;
                ldm4(q0, q1, q2, q3, Kh + off);
                bh[0][0] = q0; bh[0][1] = q1; bh[1][0] = q2; bh[1][1] = q3;
                ldm4(q0, q1, q2, q3, Kl + off);
                bl[0][0] = q0; bl[0][1] = q1; bl[1][0] = q2; bl[1][1] = q3;
            }
#pragma unroll
            for (int mi = 0; mi < 2; mi++)
#pragma unroll
                for (int nf = 0; nf < 2; nf++) {
                    mma16816(acc[mi][nf], ah[mi], bh[nf]);
                    mma16816(acc[mi][nf], al[mi], bh[nf]);
                    mma16816(acc[mi][nf], ah[mi], bl[nf]);
                }
        }
        // store S tile (fp32, stride 66)
#pragma unroll
        for (int mi = 0; mi < 2; mi++)
#pragma unroll
            for (int nf = 0; nf < 2; nf++) {
                int r0 = wm * 32 + mi * 16 + trow;
                int col = wn * 16 + nf * 8 + tcol;
                *(float2*)&Sf[r0 * 66 + col] =
                    make_float2(acc[mi][nf][0], acc[mi][nf][1]);
                *(float2*)&Sf[(r0 + 8) * 66 + col] =
                    make_float2(acc[mi][nf][2], acc[mi][nf][3]);
            }
        __syncthreads();

        // ---- online softmax: one row per quad of threads ----
        {
            int r = tid >> 2, seg = tid & 3;
            float vals[16];
            float* bp = &Sf[r * 66 + seg * 16];
#pragma unroll
            for (int i = 0; i < 8; i++) {
                float2 t2 = *(float2*)(bp + 2 * i);
                vals[2 * i] = t2.x; vals[2 * i + 1] = t2.y;
            }
            float mt = vals[0];
#pragma unroll
            for (int i = 1; i < 16; i++) mt = fmaxf(mt, vals[i]);
            mt = fmaxf(mt, __shfl_xor_sync(~0u, mt, 1));
            mt = fmaxf(mt, __shfl_xor_sync(~0u, mt, 2));
            float mo = smM[r];
            float mn = fmaxf(mo, mt);
            float f = __expf(mo - mn);
            float sum = 0.f;
            __half* pp = &Pm[r * 72 + seg * 16];
#pragma unroll
            for (int i = 0; i < 8; i++) {
                float e0 = __expf(vals[2 * i] - mn);
                float e1 = __expf(vals[2 * i + 1] - mn);
                *(__half2*)(pp + 2 * i) = __floats2half2_rn(e0, e1);
                sum += e0 + e1;
            }
            sum += __shfl_xor_sync(~0u, sum, 1);
            sum += __shfl_xor_sync(~0u, sum, 2);
            if (seg == 0) {
                smM[r] = mn;
                smL[r] = smL[r] * f + sum;
                smF[r] = f;
            }
        }
        __syncthreads();

        // ---- PV phase: warp tile 32(m) x 32(n cols), K=64 keys ----
#pragma unroll
        for (int mi = 0; mi < 2; mi++) {
            float f0 = smF[wm * 32 + mi * 16 + trow];
            float f1 = smF[wm * 32 + mi * 16 + trow + 8];
#pragma unroll
            for (int nf = 0; nf < 4; nf++) {
                O[mi][nf][0] *= f0; O[mi][nf][1] *= f0;
                O[mi][nf][2] *= f1; O[mi][nf][3] *= f1;
            }
        }
#pragma unroll
        for (int ks = 0; ks < 4; ks++) {
            const int k0 = ks * 16;
            unsigned aP[2][4];
#pragma unroll
            for (int mi = 0; mi < 2; mi++) {
                unsigned off = (unsigned)((wm * 32 + mi * 16 + r8 + (sub & 1) * 8) * 72 +
                                          k0 + (sub >> 1) * 8) * 2;
                ldm4(aP[mi][0], aP[mi][1], aP[mi][2], aP[mi][3], sb + OFF_P + off);
            }
            unsigned bV[4][2];
#pragma unroll
            for (int np = 0; np < 2; np++) {
                unsigned off = (unsigned)((wn * 32 + np * 16 + r8 + (sub >> 1) * 8) * 72 +
                                          k0 + (sub & 1) * 8) * 2;
                unsigned q0, q1, q2, q3;
                ldm4(q0, q1, q2, q3, Vb + off);
                bV[np * 2][0] = q0; bV[np * 2][1] = q1;
                bV[np * 2 + 1][0] = q2; bV[np * 2 + 1][1] = q3;
            }
#pragma unroll
            for (int mi = 0; mi < 2; mi++)
#pragma unroll
                for (int nf = 0; nf < 4; nf++)
                    mma16816(O[mi][nf], aP[mi], bV[nf]);
        }
    }
#undef LOAD_KV

    // ---- epilogue: normalize, split cols node/pos, pair-write hi/lo ----
    const long long coff = 128LL * h + 1048576LL * b;
#pragma unroll
    for (int mi = 0; mi < 2; mi++) {
        int r0 = wm * 32 + mi * 16 + trow;
        float inv0 = 1.f / smL[r0], inv1 = 1.f / smL[r0 + 8];
        int rg0 = qt * 128 + r0, rg1 = rg0 + 8;
#pragma unroll
        for (int nf = 0; nf < 4; nf++) {
            int cg = wn * 32 + nf * 8 + tcol;
            __half* hB = (cg < 64) ? C0 : C2;
            __half* lB = (cg < 64) ? C1 : C3;
            int cl = cg & 63;
            size_t o0 = coff + (size_t)rg0 * 1024 + cl;
            size_t o1 = coff + (size_t)rg1 * 1024 + cl;
            __half2 hh, ll;
            split2(O[mi][nf][0] * inv0, O[mi][nf][1] * inv0, hh, ll);
            *(__half2*)(hB + o0) = hh;
            *(__half2*)(lB + o0) = ll;
            split2(O[mi][nf][2] * inv1, O[mi][nf][3] * inv1, hh, ll);
            *(__half2*)(hB + o1) = hh;
            *(__half2*)(lB + o1) = ll;
        }
    }
}

// ---------------------------------------------------------------------------
// Prep kernels (pair outputs)
// ---------------------------------------------------------------------------
__global__ void cvt_pair(const float* __restrict__ X, __half* __restrict__ Yh,
                         __half* __restrict__ Yl, int n4) {
    int i = blockIdx.x * blockDim.x + threadIdx.x;
    if (i >= n4) return;
    float4 v = ((const float4*)X)[i];
    __half2 h0, l0, h1, l1;
    split2(v.x, v.y, h0, l0);
    split2(v.z, v.w, h1, l1);
    uint2 uh, ul;
    uh.x = *reinterpret_cast<unsigned*>(&h0);
    uh.y = *reinterpret_cast<unsigned*>(&h1);
    ul.x = *reinterpret_cast<unsigned*>(&l0);
    ul.y = *reinterpret_cast<unsigned*>(&l1);
    ((uint2*)Yh)[i] = uh;
    ((uint2*)Yl)[i] = ul;
}

__global__ void repack_qk(const float* __restrict__ Wq, const float* __restrict__ Wk,
                          __half* __restrict__ WTh, __half* __restrict__ WTl) {
    int idx = blockIdx.x * blockDim.x + threadIdx.x;
    if (idx >= 1024 * 512) return;
    int j = idx >> 9, d = idx & 511;
    int jj = j & 511;
    float v;
    if (j < 512)
        v = Wq[((size_t)((jj >> 6) * 512 + d)) * 64 + (jj & 63)] * 0.125f;
    else
        v = Wk[((size_t)((jj >> 6) * 512 + d)) * 64 + (jj & 63)];
    __half h = __float2half_rn(v);
    WTh[idx] = h;
    WTl[idx] = __float2half_rn(v - __half2float(h));
}

__global__ void repack_v(const float* __restrict__ Wv, __half* __restrict__ WTh,
                         __half* __restrict__ WTl) {
    int idx = blockIdx.x * blockDim.x + threadIdx.x;
    if (idx >= 1024 * 512) return;
    int j = idx >> 9, d = idx & 511;
    float v = Wv[((size_t)((j >> 6) * 512 + d)) * 64 + (j & 63)];
    __half h = __float2half_rn(v);
    WTh[idx] = h;
    WTl[idx] = __float2half_rn(v - __half2float(h));
}

__global__ void repack_wo(const float* __restrict__ Wo, __half* __restrict__ WTh,
                          __half* __restrict__ WTl) {
    int idx = blockIdx.x * blockDim.x + threadIdx.x;
    if (idx >= 512 * 1024) return;
    int e = idx >> 10, j = idx & 1023;
    float v = Wo[(size_t)j * 512 + e];
    __half h = __float2half_rn(v);
    WTh[idx] = h;
    WTl[idx] = __float2half_rn(v - __half2float(h));
}

// ---------------------------------------------------------------------------
// Host launcher
// ---------------------------------------------------------------------------
extern "C" void kernel_launch(void* const* d_in, const int* in_sizes, int n_in,
                              void* d_out, int out_size) {
    const float* Xn  = (const float*)d_in[0];
    const float* Xp  = (const float*)d_in[1];
    const float* Wqn = (const float*)d_in[2];
    const float* Wqp = (const float*)d_in[3];
    const float* Wkn = (const float*)d_in[4];
    const float* Wkp = (const float*)d_in[5];
    const float* Wvn = (const float*)d_in[6];
    const float* Wvp = (const float*)d_in[7];
    const float* Won = (const float*)d_in[8];
    const float* Wop = (const float*)d_in[9];
    float* out = (float*)d_out;

    __half *WnTh, *WnTl, *WpTh, *WpTl, *WvnTh, *WvnTl, *WvpTh, *WvpTl;
    __half *WonTh, *WonTl, *WopTh, *WopTl;
    __half *Xnh, *Xnl, *Xph, *Xpl, *QKnh, *QKnl, *QKph, *QKpl;
    __half *Vth, *Vtl, *Hnh, *Hnl, *Hph, *Hpl;
    cudaGetSymbolAddress((void**)&WnTh,  g_WnTh);
    cudaGetSymbolAddress((void**)&WnTl,  g_WnTl);
    cudaGetSymbolAddress((void**)&WpTh,  g_WpTh);
    cudaGetSymbolAddress((void**)&WpTl,  g_WpTl);
    cudaGetSymbolAddress((void**)&WvnTh, g_WvnTh);
    cudaGetSymbolAddress((void**)&WvnTl, g_WvnTl);
    cudaGetSymbolAddress((void**)&WvpTh, g_WvpTh);
    cudaGetSymbolAddress((void**)&WvpTl, g_WvpTl);
    cudaGetSymbolAddress((void**)&WonTh, g_WonTh);
    cudaGetSymbolAddress((void**)&WonTl, g_WonTl);
    cudaGetSymbolAddress((void**)&WopTh, g_WopTh);
    cudaGetSymbolAddress((void**)&WopTl, g_WopTl);
    cudaGetSymbolAddress((void**)&Xnh,   g_Xnh);
    cudaGetSymbolAddress((void**)&Xnl,   g_Xnl);
    cudaGetSymbolAddress((void**)&Xph,   g_Xph);
    cudaGetSymbolAddress((void**)&Xpl,   g_Xpl);
    cudaGetSymbolAddress((void**)&QKnh,  g_QKnh);
    cudaGetSymbolAddress((void**)&QKnl,  g_QKnl);
    cudaGetSymbolAddress((void**)&QKph,  g_QKph);
    cudaGetSymbolAddress((void**)&QKpl,  g_QKpl);
    cudaGetSymbolAddress((void**)&Vth,   g_Vth);
    cudaGetSymbolAddress((void**)&Vtl,   g_Vtl);
    cudaGetSymbolAddress((void**)&Hnh,   g_Hnh);
    cudaGetSymbolAddress((void**)&Hnl,   g_Hnl);
    cudaGetSymbolAddress((void**)&Hph,   g_Hph);
    cudaGetSymbolAddress((void**)&Hpl,   g_Hpl);

    cudaFuncSetAttribute(hgemm, cudaFuncAttributeMaxDynamicSharedMemorySize,
                         GEMM_SMEM);
    cudaFuncSetAttribute(flash_attn, cudaFuncAttributeMaxDynamicSharedMemorySize,
                         FA_SMEM);

    // 1) repacks + conversions
    repack_qk<<<2048, 256>>>(Wqn, Wkn, WnTh, WnTl);
    repack_qk<<<2048, 256>>>(Wqp, Wkp, WpTh, WpTl);
    repack_v <<<2048, 256>>>(Wvn, WvnTh, WvnTl);
    repack_v <<<2048, 256>>>(Wvp, WvpTh, WvpTl);
    repack_wo<<<2048, 256>>>(Won, WonTh, WonTl);
    repack_wo<<<2048, 256>>>(Wop, WopTh, WopTl);
    cvt_pair<<<8192, 256>>>(Xn, Xnh, Xnl, ROWS * 512 / 4);
    cvt_pair<<<8192, 256>>>(Xp, Xph, Xpl, ROWS * 512 / 4);

    // 2) Q,K projections, 3-term, pair out
    hgemm<<<dim3(8, 128, 1), 512, GEMM_SMEM>>>(
        Xnh, Xnl, Xnh, 0, 0, 512,
        WnTh, WnTh, WnTl, 0, 0, 512,
        QKnh, QKnl, 0, 0, 1024, 512, 3, 4, 0);
    hgemm<<<dim3(8, 128, 1), 512, GEMM_SMEM>>>(
        Xph, Xpl, Xph, 0, 0, 512,
        WpTh, WpTh, WpTl, 0, 0, 512,
        QKph, QKpl, 0, 0, 1024, 512, 3, 4, 0);

    // 3) V transposed, 3-term, pair out with row remap
    hgemm<<<dim3(128, 8, 1), 512, GEMM_SMEM>>>(
        WvnTh, WvnTl, WvnTh, 0, 0, 512,
        Xnh, Xnh, Xnl, 0, 0, 512,
        Vth, Vtl, 0, 0, ROWS, 512, 3, 5, 0);
    hgemm<<<dim3(128, 8, 1), 512, GEMM_SMEM>>>(
        WvpTh, WvpTl, WvpTh, 0, 0, 512,
        Xph, Xph, Xpl, 0, 0, 512,
        Vth, Vtl, 0, 0, ROWS, 512, 3, 5, 64);

    // 4) fused flash attention per softmax stream
    for (int s = 0; s < 2; s++) {
        const __half* Qh = s ? QKph : QKnh;
        const __half* Ql = s ? QKpl : QKnl;
        flash_attn<<<dim3(8, 128), 512, FA_SMEM>>>(
            Qh, Ql, Vth + (size_t)s * 16777216,
            Hnh + s * 64, Hnl + s * 64, Hph + s * 64, Hpl + s * 64);
    }

    // 5) output projections, 3-term, fp32 out
    hgemm<<<dim3(4, 128, 1), 512, GEMM_SMEM>>>(
        Hnh, Hnl, Hnh, 0, 0, 1024,
        WonTh, WonTh, WonTl, 0, 0, 1024,
        out, nullptr, 0, 0, 512, 1024, 3, 1, 0);
    hgemm<<<dim3(4, 128, 1), 512, GEMM_SMEM>>>(
        Hph, Hpl, Hph, 0, 0, 1024,
        WopTh, WopTh, WopTl, 0, 0, 1024,
        out + (size_t)ROWS * 512, nullptr, 0, 0, 512, 1024, 3, 1, 0);
}

// round 6
// speedup vs baseline: 3.5551x; 1.1338x over previous
#include <cuda_runtime.h>
#include <cuda_fp16.h>

// ===========================================================================
// B=16, N=1024, D=512, H=8, dk=64. ROWS=16384.
// HMMA (mma.sync m16n8k16) everywhere, fp32 accum, split-fp16 (hi+lo).
// QK proj + S: 3-term. V proj, out proj: 2-term. PV: V-hi only.
// ===========================================================================
#define ROWS 16384
#define PADK 72
#define TILEB (128 * PADK * 2)
#define GEMM_SMEM (4 * TILEB)

// Fused attention smem layout (bytes)
#define NKT   16
#define OFF_Q  0                    // Qhi 18432 + Qlo 18432
#define OFF_KV 36864                // 2 bufs x (Khi 9216 | Klo 9216 | V 18432)
#define KVBUF  36864
#define OFF_S  110592               // 128*66*4 fp32
#define OFF_P  144384               // 128*72*2 fp16
#define OFF_M  162816               // 128 fp32 row-max
#define OFF_L  163328               // 128 fp32 row-sum
#define OFF_F  163840               // 128 fp32 rescale
#define FA_SMEM 164352

// ---------------------------------------------------------------------------
// Static device scratch
// ---------------------------------------------------------------------------
__device__ __half g_WnTh [1024 * 512], g_WnTl [1024 * 512];
__device__ __half g_WpTh [1024 * 512], g_WpTl [1024 * 512];
__device__ __half g_WvnTh[1024 * 512], g_WvnTl[1024 * 512];
__device__ __half g_WvpTh[1024 * 512], g_WvpTl[1024 * 512];
__device__ __half g_WonTh[512 * 1024], g_WonTl[512 * 1024];
__device__ __half g_WopTh[512 * 1024], g_WopTl[512 * 1024];
__device__ __half g_Xnh[(size_t)ROWS * 512], g_Xnl[(size_t)ROWS * 512];
__device__ __half g_Xph[(size_t)ROWS * 512], g_Xpl[(size_t)ROWS * 512];
__device__ __half g_QKnh[(size_t)ROWS * 1024], g_QKnl[(size_t)ROWS * 1024];
__device__ __half g_QKph[(size_t)ROWS * 1024], g_QKpl[(size_t)ROWS * 1024];
__device__ __half g_Vth[(size_t)2048 * ROWS];
__device__ __half g_Hnh[(size_t)ROWS * 1024], g_Hnl[(size_t)ROWS * 1024];
__device__ __half g_Hph[(size_t)ROWS * 1024], g_Hpl[(size_t)ROWS * 1024];

// ---------------------------------------------------------------------------
// PTX helpers
// ---------------------------------------------------------------------------
__device__ __forceinline__ unsigned smem_u32(const void* p) {
    unsigned a;
    asm("{ .reg .u64 t; cvta.to.shared.u64 t, %1; cvt.u32.u64 %0, t; }"
        : "=r"(a) : "l"(p));
    return a;
}
__device__ __forceinline__ void cpasync16(unsigned s, const void* g) {
    asm volatile("cp.async.cg.shared.global [%0], [%1], 16;" :: "r"(s), "l"(g));
}
__device__ __forceinline__ void cp_commit() {
    asm volatile("cp.async.commit_group;" ::: "memory");
}
__device__ __forceinline__ void cp_wait0() {
    asm volatile("cp.async.wait_group 0;" ::: "memory");
}
__device__ __forceinline__ void ldm4(unsigned& r0, unsigned& r1, unsigned& r2,
                                     unsigned& r3, unsigned a) {
    asm volatile("ldmatrix.sync.aligned.m8n8.x4.shared.b16 {%0,%1,%2,%3}, [%4];"
                 : "=r"(r0), "=r"(r1), "=r"(r2), "=r"(r3) : "r"(a));
}
__device__ __forceinline__ void mma16816(float* c, const unsigned* a,
                                         const unsigned* b) {
    asm volatile(
        "mma.sync.aligned.m16n8k16.row.col.f32.f16.f16.f32 "
        "{%0,%1,%2,%3}, {%4,%5,%6,%7}, {%8,%9}, {%0,%1,%2,%3};"
        : "+f"(c[0]), "+f"(c[1]), "+f"(c[2]), "+f"(c[3])
        : "r"(a[0]), "r"(a[1]), "r"(a[2]), "r"(a[3]), "r"(b[0]), "r"(b[1]));
}
__device__ __forceinline__ void split2(float v0, float v1, __half2& hi, __half2& lo) {
    __half h0 = __float2half_rn(v0), h1 = __float2half_rn(v1);
    __half l0 = __float2half_rn(v0 - __half2float(h0));
    __half l1 = __float2half_rn(v1 - __half2float(h1));
    hi = __halves2half2(h0, h1);
    lo = __halves2half2(l0, l1);
}

// ---------------------------------------------------------------------------
// Multi-term HMMA GEMM: C = sum_t At(M,K)*Bt(N,K)^T, fp16 in, fp32 accum.
// modes: 1 fp32 out | 4 fp16 pair out | 7 fp16 single out + V row remap
// ---------------------------------------------------------------------------
__global__ __launch_bounds__(512)
void hgemm(const __half* __restrict__ A0, const __half* __restrict__ A1,
           const __half* __restrict__ A2,
           long long sAh, long long sAb, int lda,
           const __half* __restrict__ B0, const __half* __restrict__ B1,
           const __half* __restrict__ B2,
           long long sBh, long long sBb, int ldb,
           void* __restrict__ C0, void* __restrict__ C1,
           long long sCh, long long sCb, int ldc,
           int Kper, int nterm, int mode, int halfoff) {
    extern __shared__ __align__(16) char smem[];
    const unsigned smA = smem_u32(smem);
    const unsigned smB = smA + 2 * TILEB;

    const int tid = threadIdx.x;
    const int wid = tid >> 5, lane = tid & 31;
    const int wm = wid & 3, wn = wid >> 2;

    const int zh = (int)(blockIdx.z >> 4), zb = (int)(blockIdx.z & 15);
    const long long aoff = sAh * zh + sAb * zb + (long long)(blockIdx.y * 128) * lda;
    const long long boff = sBh * zh + sBb * zb + (long long)(blockIdx.x * 128) * ldb;
    const __half* At[3] = {A0 + aoff, A1 + aoff, A2 + aoff};
    const __half* Bt[3] = {B0 + boff, B1 + boff, B2 + boff};

    const int r0c = tid >> 3, s0c = tid & 7;
    const int r1c = r0c + 64;
    const int trA0 = r0c * lda + s0c * 8, trA1 = r1c * lda + s0c * 8;
    const int trB0 = r0c * ldb + s0c * 8, trB1 = r1c * ldb + s0c * 8;
    const unsigned so0 = (unsigned)(r0c * PADK + s0c * 8) * 2;
    const unsigned so1 = (unsigned)(r1c * PADK + s0c * 8) * 2;

    const int T = Kper >> 6;
    const int TT = nterm * T;

#define LOAD_TILE(g, bf)                                                      \
    do {                                                                      \
        int t_ = ((g) >= T) + ((g) >= 2 * T);                                 \
        int kk_ = (g) - t_ * T;                                               \
        const __half* ap = At[t_] + kk_ * 64;                                 \
        const __half* bp = Bt[t_] + kk_ * 64;                                 \
        cpasync16(smA + (bf) * TILEB + so0, ap + trA0);                       \
        cpasync16(smA + (bf) * TILEB + so1, ap + trA1);                       \
        cpasync16(smB + (bf) * TILEB + so0, bp + trB0);                       \
        cpasync16(smB + (bf) * TILEB + so1, bp + trB1);                       \
        cp_commit();                                                          \
    } while (0)

    LOAD_TILE(0, 0);

    float acc[2][4][4];
#pragma unroll
    for (int i = 0; i < 2; i++)
#pragma unroll
        for (int j = 0; j < 4; j++)
#pragma unroll
            for (int k = 0; k < 4; k++) acc[i][j][k] = 0.f;

    const int sub = lane >> 3, r8 = lane & 7;

    for (int g = 0; g < TT; g++) {
        const int bf = g & 1;
        cp_wait0();
        __syncthreads();
        if (g + 1 < TT) LOAD_TILE(g + 1, bf ^ 1);

        const unsigned ab = smA + bf * TILEB;
        const unsigned bb = smB + bf * TILEB;
#pragma unroll
        for (int ks = 0; ks < 4; ks++) {
            const int k0 = ks * 16;
            unsigned a[2][4];
#pragma unroll
            for (int mi = 0; mi < 2; mi++) {
                int mrow = wm * 32 + mi * 16 + r8 + (sub & 1) * 8;
                int mcol = k0 + (sub >> 1) * 8;
                ldm4(a[mi][0], a[mi][1], a[mi][2], a[mi][3],
                     ab + (unsigned)(mrow * PADK + mcol) * 2);
            }
            unsigned b[4][2];
#pragma unroll
            for (int np = 0; np < 2; np++) {
                int nrow = wn * 32 + np * 16 + r8 + (sub >> 1) * 8;
                int kcol = k0 + (sub & 1) * 8;
                unsigned q0, q1, q2, q3;
                ldm4(q0, q1, q2, q3, bb + (unsigned)(nrow * PADK + kcol) * 2);
                b[np * 2][0] = q0; b[np * 2][1] = q1;
                b[np * 2 + 1][0] = q2; b[np * 2 + 1][1] = q3;
            }
#pragma unroll
            for (int mi = 0; mi < 2; mi++)
#pragma unroll
                for (int ni = 0; ni < 4; ni++)
                    mma16816(acc[mi][ni], a[mi], b[ni]);
        }
        __syncthreads();
    }
#undef LOAD_TILE

    const int trow = lane >> 2, tcol = (lane & 3) * 2;
    const long long coff = sCh * zh + sCb * zb;

#pragma unroll
    for (int mi = 0; mi < 2; mi++) {
#pragma unroll
        for (int ni = 0; ni < 4; ni++) {
            int rg = blockIdx.y * 128 + wm * 32 + mi * 16 + trow;
            int cg = blockIdx.x * 128 + wn * 32 + ni * 8 + tcol;
            float* ac = acc[mi][ni];
            if (mode == 1) {
                float* p0 = (float*)C0 + coff + (size_t)rg * ldc + cg;
                float* p1 = (float*)C0 + coff + (size_t)(rg + 8) * ldc + cg;
                *(float2*)p0 = make_float2(ac[0], ac[1]);
                *(float2*)p1 = make_float2(ac[2], ac[3]);
            } else if (mode == 4) {
                __half2 h, l;
                size_t o0 = coff + (size_t)rg * ldc + cg;
                size_t o1 = coff + (size_t)(rg + 8) * ldc + cg;
                split2(ac[0], ac[1], h, l);
                *(__half2*)((__half*)C0 + o0) = h;
                *(__half2*)((__half*)C1 + o0) = l;
                split2(ac[2], ac[3], h, l);
                *(__half2*)((__half*)C0 + o1) = h;
                *(__half2*)((__half*)C1 + o1) = l;
            } else {  // mode 7: single fp16 out + V row remap
                int ra = ((rg >> 6) << 7) + (rg & 63) + halfoff;
                int rb0 = rg + 8;
                int rb = ((rb0 >> 6) << 7) + (rb0 & 63) + halfoff;
                *(__half2*)((__half*)C0 + coff + (size_t)ra * ldc + cg) =
                    __floats2half2_rn(ac[0], ac[1]);
                *(__half2*)((__half*)C0 + coff + (size_t)rb * ldc + cg) =
                    __floats2half2_rn(ac[2], ac[3]);
            }
        }
    }
}

// ---------------------------------------------------------------------------
// Fused flash attention (unchanged from R5).
// ---------------------------------------------------------------------------
__global__ __launch_bounds__(512)
void flash_attn(const __half* __restrict__ QKh, const __half* __restrict__ QKl,
                const __half* __restrict__ Vh,
                __half* __restrict__ C0, __half* __restrict__ C1,
                __half* __restrict__ C2, __half* __restrict__ C3) {
    extern __shared__ __align__(16) char smem[];
    const unsigned sb = smem_u32(smem);
    float* Sf  = (float*)(smem + OFF_S);
    __half* Pm = (__half*)(smem + OFF_P);
    float* smM = (float*)(smem + OFF_M);
    float* smL = (float*)(smem + OFF_L);
    float* smF = (float*)(smem + OFF_F);

    const int tid = threadIdx.x, wid = tid >> 5, lane = tid & 31;
    const int wm = wid & 3, wn = wid >> 2;
    const int sub = lane >> 3, r8 = lane & 7;
    const int trow = lane >> 2, tcol = (lane & 3) * 2;
    const int qt = blockIdx.x, z = blockIdx.y;
    const int h = z >> 4, b = z & 15;

    if (tid < 128) { smM[tid] = -1e30f; smL[tid] = 0.f; }

    {
        const size_t rbase = (size_t)(b << 10) + qt * 128;
        int c0 = tid, c1 = tid + 512;
        int r0 = c0 >> 3, s0 = c0 & 7, r1 = c1 >> 3, s1 = c1 & 7;
        int col0 = h * 64 + s0 * 8, col1 = h * 64 + s1 * 8;
        cpasync16(sb + OFF_Q + (unsigned)(r0 * 72 + s0 * 8) * 2,
                  QKh + (rbase + r0) * 1024 + col0);
        cpasync16(sb + OFF_Q + (unsigned)(r1 * 72 + s1 * 8) * 2,
                  QKh + (rbase + r1) * 1024 + col1);
        cpasync16(sb + OFF_Q + 18432 + (unsigned)(r0 * 72 + s0 * 8) * 2,
                  QKl + (rbase + r0) * 1024 + col0);
        cpasync16(sb + OFF_Q + 18432 + (unsigned)(r1 * 72 + s1 * 8) * 2,
                  QKl + (rbase + r1) * 1024 + col1);
    }

#define LOAD_KV(kt, bi)                                                       \
    do {                                                                      \
        int rr = tid >> 3, ss = tid & 7;                                      \
        size_t gr = (size_t)(b << 10) + (kt) * 64 + rr;                       \
        unsigned sof = (unsigned)(rr * 72 + ss * 8) * 2;                      \
        cpasync16(sb + OFF_KV + (bi) * KVBUF + sof,                           \
                  QKh + gr * 1024 + 512 + h * 64 + ss * 8);                   \
        cpasync16(sb + OFF_KV + (bi) * KVBUF + 9216 + sof,                    \
                  QKl + gr * 1024 + 512 + h * 64 + ss * 8);                   \
        int v0 = tid, v1 = tid + 512;                                         \
        int vr0 = v0 >> 3, vs0 = v0 & 7, vr1 = v1 >> 3, vs1 = v1 & 7;         \
        size_t vcb = (size_t)(b << 10) + (kt) * 64;                           \
        cpasync16(sb + OFF_KV + (bi) * KVBUF + 18432 +                        \
                      (unsigned)(vr0 * 72 + vs0 * 8) * 2,                     \
                  Vh + (size_t)(h * 128 + vr0) * 16384 + vcb + vs0 * 8);      \
        cpasync16(sb + OFF_KV + (bi) * KVBUF + 18432 +                        \
                      (unsigned)(vr1 * 72 + vs1 * 8) * 2,                     \
                  Vh + (size_t)(h * 128 + vr1) * 16384 + vcb + vs1 * 8);      \
        cp_commit();                                                          \
    } while (0)

    LOAD_KV(0, 0);
    cp_wait0();

    float O[2][4][4] = {};

    for (int kt = 0; kt < NKT; kt++) {
        const int bi = kt & 1;
        if (kt) cp_wait0();
        __syncthreads();
        if (kt + 1 < NKT) LOAD_KV(kt + 1, bi ^ 1);

        const unsigned Kh = sb + OFF_KV + bi * KVBUF;
        const unsigned Kl = Kh + 9216;
        const unsigned Vb = Kh + 18432;

        float acc[2][2][4] = {};
#pragma unroll
        for (int ks = 0; ks < 4; ks++) {
            const int k0 = ks * 16;
            unsigned ah[2][4], al[2][4];
#pragma unroll
            for (int mi = 0; mi < 2; mi++) {
                unsigned off = (unsigned)((wm * 32 + mi * 16 + r8 + (sub & 1) * 8) * 72 +
                                          k0 + (sub >> 1) * 8) * 2;
                ldm4(ah[mi][0], ah[mi][1], ah[mi][2], ah[mi][3], sb + OFF_Q + off);
                ldm4(al[mi][0], al[mi][1], al[mi][2], al[mi][3],
                     sb + OFF_Q + 18432 + off);
            }
            unsigned bh[2][2], bl[2][2];
            {
                unsigned off = (unsigned)((wn * 16 + r8 + (sub >> 1) * 8) * 72 +
                                          k0 + (sub & 1) * 8) * 2;
                unsigned q0, q1, q2, q3;
                ldm4(q0, q1, q2, q3, Kh + off);
                bh[0][0] = q0; bh[0][1] = q1; bh[1][0] = q2; bh[1][1] = q3;
                ldm4(q0, q1, q2, q3, Kl + off);
                bl[0][0] = q0; bl[0][1] = q1; bl[1][0] = q2; bl[1][1] = q3;
            }
#pragma unroll
            for (int mi = 0; mi < 2; mi++)
#pragma unroll
                for (int nf = 0; nf < 2; nf++) {
                    mma16816(acc[mi][nf], ah[mi], bh[nf]);
                    mma16816(acc[mi][nf], al[mi], bh[nf]);
                    mma16816(acc[mi][nf], ah[mi], bl[nf]);
                }
        }
#pragma unroll
        for (int mi = 0; mi < 2; mi++)
#pragma unroll
            for (int nf = 0; nf < 2; nf++) {
                int r0 = wm * 32 + mi * 16 + trow;
                int col = wn * 16 + nf * 8 + tcol;
                *(float2*)&Sf[r0 * 66 + col] =
                    make_float2(acc[mi][nf][0], acc[mi][nf][1]);
                *(float2*)&Sf[(r0 + 8) * 66 + col] =
                    make_float2(acc[mi][nf][2], acc[mi][nf][3]);
            }
        __syncthreads();

        {
            int r = tid >> 2, seg = tid & 3;
            float vals[16];
            float* bp = &Sf[r * 66 + seg * 16];
#pragma unroll
            for (int i = 0; i < 8; i++) {
                float2 t2 = *(float2*)(bp + 2 * i);
                vals[2 * i] = t2.x; vals[2 * i + 1] = t2.y;
            }
            float mt = vals[0];
#pragma unroll
            for (int i = 1; i < 16; i++) mt = fmaxf(mt, vals[i]);
            mt = fmaxf(mt, __shfl_xor_sync(~0u, mt, 1));
            mt = fmaxf(mt, __shfl_xor_sync(~0u, mt, 2));
            float mo = smM[r];
            float mn = fmaxf(mo, mt);
            float f = __expf(mo - mn);
            float sum = 0.f;
            __half* pp = &Pm[r * 72 + seg * 16];
#pragma unroll
            for (int i = 0; i < 8; i++) {
                float e0 = __expf(vals[2 * i] - mn);
                float e1 = __expf(vals[2 * i + 1] - mn);
                *(__half2*)(pp + 2 * i) = __floats2half2_rn(e0, e1);
                sum += e0 + e1;
            }
            sum += __shfl_xor_sync(~0u, sum, 1);
            sum += __shfl_xor_sync(~0u, sum, 2);
            if (seg == 0) {
                smM[r] = mn;
                smL[r] = smL[r] * f + sum;
                smF[r] = f;
            }
        }
        __syncthreads();

#pragma unroll
        for (int mi = 0; mi < 2; mi++) {
            float f0 = smF[wm * 32 + mi * 16 + trow];
            float f1 = smF[wm * 32 + mi * 16 + trow + 8];
#pragma unroll
            for (int nf = 0; nf < 4; nf++) {
                O[mi][nf][0] *= f0; O[mi][nf][1] *= f0;
                O[mi][nf][2] *= f1; O[mi][nf][3] *= f1;
            }
        }
#pragma unroll
        for (int ks = 0; ks < 4; ks++) {
            const int k0 = ks * 16;
            unsigned aP[2][4];
#pragma unroll
            for (int mi = 0; mi < 2; mi++) {
                unsigned off = (unsigned)((wm * 32 + mi * 16 + r8 + (sub & 1) * 8) * 72 +
                                          k0 + (sub >> 1) * 8) * 2;
                ldm4(aP[mi][0], aP[mi][1], aP[mi][2], aP[mi][3], sb + OFF_P + off);
            }
            unsigned bV[4][2];
#pragma unroll
            for (int np = 0; np < 2; np++) {
                unsigned off = (unsigned)((wn * 32 + np * 16 + r8 + (sub >> 1) * 8) * 72 +
                                          k0 + (sub & 1) * 8) * 2;
                unsigned q0, q1, q2, q3;
                ldm4(q0, q1, q2, q3, Vb + off);
                bV[np * 2][0] = q0; bV[np * 2][1] = q1;
                bV[np * 2 + 1][0] = q2; bV[np * 2 + 1][1] = q3;
            }
#pragma unroll
            for (int mi = 0; mi < 2; mi++)
#pragma unroll
                for (int nf = 0; nf < 4; nf++)
                    mma16816(O[mi][nf], aP[mi], bV[nf]);
        }
    }
#undef LOAD_KV

    const long long coff = 128LL * h + 1048576LL * b;
#pragma unroll
    for (int mi = 0; mi < 2; mi++) {
        int r0 = wm * 32 + mi * 16 + trow;
        float inv0 = 1.f / smL[r0], inv1 = 1.f / smL[r0 + 8];
        int rg0 = qt * 128 + r0, rg1 = rg0 + 8;
#pragma unroll
        for (int nf = 0; nf < 4; nf++) {
            int cg = wn * 32 + nf * 8 + tcol;
            __half* hB = (cg < 64) ? C0 : C2;
            __half* lB = (cg < 64) ? C1 : C3;
            int cl = cg & 63;
            size_t o0 = coff + (size_t)rg0 * 1024 + cl;
            size_t o1 = coff + (size_t)rg1 * 1024 + cl;
            __half2 hh, ll;
            split2(O[mi][nf][0] * inv0, O[mi][nf][1] * inv0, hh, ll);
            *(__half2*)(hB + o0) = hh;
            *(__half2*)(lB + o0) = ll;
            split2(O[mi][nf][2] * inv1, O[mi][nf][3] * inv1, hh, ll);
            *(__half2*)(hB + o1) = hh;
            *(__half2*)(lB + o1) = ll;
        }
    }
}

// ---------------------------------------------------------------------------
// Prep kernels
// ---------------------------------------------------------------------------
__global__ void cvt_pair(const float* __restrict__ X, __half* __restrict__ Yh,
                         __half* __restrict__ Yl, int n4) {
    int i = blockIdx.x * blockDim.x + threadIdx.x;
    if (i >= n4) return;
    float4 v = ((const float4*)X)[i];
    __half2 h0, l0, h1, l1;
    split2(v.x, v.y, h0, l0);
    split2(v.z, v.w, h1, l1);
    uint2 uh, ul;
    uh.x = *reinterpret_cast<unsigned*>(&h0);
    uh.y = *reinterpret_cast<unsigned*>(&h1);
    ul.x = *reinterpret_cast<unsigned*>(&l0);
    ul.y = *reinterpret_cast<unsigned*>(&l1);
    ((uint2*)Yh)[i] = uh;
    ((uint2*)Yl)[i] = ul;
}

__global__ void repack_qk(const float* __restrict__ Wq, const float* __restrict__ Wk,
                          __half* __restrict__ WTh, __half* __restrict__ WTl) {
    int idx = blockIdx.x * blockDim.x + threadIdx.x;
    if (idx >= 1024 * 512) return;
    int j = idx >> 9, d = idx & 511;
    int jj = j & 511;
    float v;
    if (j < 512)
        v = Wq[((size_t)((jj >> 6) * 512 + d)) * 64 + (jj & 63)] * 0.125f;
    else
        v = Wk[((size_t)((jj >> 6) * 512 + d)) * 64 + (jj & 63)];
    __half h = __float2half_rn(v);
    WTh[idx] = h;
    WTl[idx] = __float2half_rn(v - __half2float(h));
}

__global__ void repack_v(const float* __restrict__ Wv, __half* __restrict__ WTh,
                         __half* __restrict__ WTl) {
    int idx = blockIdx.x * blockDim.x + threadIdx.x;
    if (idx >= 1024 * 512) return;
    int j = idx >> 9, d = idx & 511;
    float v = Wv[((size_t)((j >> 6) * 512 + d)) * 64 + (j & 63)];
    __half h = __float2half_rn(v);
    WTh[idx] = h;
    WTl[idx] = __float2half_rn(v - __half2float(h));
}

__global__ void repack_wo(const float* __restrict__ Wo, __half* __restrict__ WTh,
                          __half* __restrict__ WTl) {
    int idx = blockIdx.x * blockDim.x + threadIdx.x;
    if (idx >= 512 * 1024) return;
    int e = idx >> 10, j = idx & 1023;
    float v = Wo[(size_t)j * 512 + e];
    __half h = __float2half_rn(v);
    WTh[idx] = h;
    WTl[idx] = __float2half_rn(v - __half2float(h));
}

// ---------------------------------------------------------------------------
// Host launcher
// ---------------------------------------------------------------------------
extern "C" void kernel_launch(void* const* d_in, const int* in_sizes, int n_in,
                              void* d_out, int out_size) {
    const float* Xn  = (const float*)d_in[0];
    const float* Xp  = (const float*)d_in[1];
    const float* Wqn = (const float*)d_in[2];
    const float* Wqp = (const float*)d_in[3];
    const float* Wkn = (const float*)d_in[4];
    const float* Wkp = (const float*)d_in[5];
    const float* Wvn = (const float*)d_in[6];
    const float* Wvp = (const float*)d_in[7];
    const float* Won = (const float*)d_in[8];
    const float* Wop = (const float*)d_in[9];
    float* out = (float*)d_out;

    __half *WnTh, *WnTl, *WpTh, *WpTl, *WvnTh, *WvnTl, *WvpTh, *WvpTl;
    __half *WonTh, *WonTl, *WopTh, *WopTl;
    __half *Xnh, *Xnl, *Xph, *Xpl, *QKnh, *QKnl, *QKph, *QKpl;
    __half *Vth, *Hnh, *Hnl, *Hph, *Hpl;
    cudaGetSymbolAddress((void**)&WnTh,  g_WnTh);
    cudaGetSymbolAddress((void**)&WnTl,  g_WnTl);
    cudaGetSymbolAddress((void**)&WpTh,  g_WpTh);
    cudaGetSymbolAddress((void**)&WpTl,  g_WpTl);
    cudaGetSymbolAddress((void**)&WvnTh, g_WvnTh);
    cudaGetSymbolAddress((void**)&WvnTl, g_WvnTl);
    cudaGetSymbolAddress((void**)&WvpTh, g_WvpTh);
    cudaGetSymbolAddress((void**)&WvpTl, g_WvpTl);
    cudaGetSymbolAddress((void**)&WonTh, g_WonTh);
    cudaGetSymbolAddress((void**)&WonTl, g_WonTl);
    cudaGetSymbolAddress((void**)&WopTh, g_WopTh);
    cudaGetSymbolAddress((void**)&WopTl, g_WopTl);
    cudaGetSymbolAddress((void**)&Xnh,   g_Xnh);
    cudaGetSymbolAddress((void**)&Xnl,   g_Xnl);
    cudaGetSymbolAddress((void**)&Xph,   g_Xph);
    cudaGetSymbolAddress((void**)&Xpl,   g_Xpl);
    cudaGetSymbolAddress((void**)&QKnh,  g_QKnh);
    cudaGetSymbolAddress((void**)&QKnl,  g_QKnl);
    cudaGetSymbolAddress((void**)&QKph,  g_QKph);
    cudaGetSymbolAddress((void**)&QKpl,  g_QKpl);
    cudaGetSymbolAddress((void**)&Vth,   g_Vth);
    cudaGetSymbolAddress((void**)&Hnh,   g_Hnh);
    cudaGetSymbolAddress((void**)&Hnl,   g_Hnl);
    cudaGetSymbolAddress((void**)&Hph,   g_Hph);
    cudaGetSymbolAddress((void**)&Hpl,   g_Hpl);

    cudaFuncSetAttribute(hgemm, cudaFuncAttributeMaxDynamicSharedMemorySize,
                         GEMM_SMEM);
    cudaFuncSetAttribute(flash_attn, cudaFuncAttributeMaxDynamicSharedMemorySize,
                         FA_SMEM);

    // 1) repacks + conversions
    repack_qk<<<2048, 256>>>(Wqn, Wkn, WnTh, WnTl);
    repack_qk<<<2048, 256>>>(Wqp, Wkp, WpTh, WpTl);
    repack_v <<<2048, 256>>>(Wvn, WvnTh, WvnTl);
    repack_v <<<2048, 256>>>(Wvp, WvpTh, WvpTl);
    repack_wo<<<2048, 256>>>(Won, WonTh, WonTl);
    repack_wo<<<2048, 256>>>(Wop, WopTh, WopTl);
    cvt_pair<<<8192, 256>>>(Xn, Xnh, Xnl, ROWS * 512 / 4);
    cvt_pair<<<8192, 256>>>(Xp, Xph, Xpl, ROWS * 512 / 4);

    // 2) Q,K projections, 3-term, pair out
    hgemm<<<dim3(8, 128, 1), 512, GEMM_SMEM>>>(
        Xnh, Xnl, Xnh, 0, 0, 512,
        WnTh, WnTh, WnTl, 0, 0, 512,
        QKnh, QKnl, 0, 0, 1024, 512, 3, 4, 0);
    hgemm<<<dim3(8, 128, 1), 512, GEMM_SMEM>>>(
        Xph, Xpl, Xph, 0, 0, 512,
        WpTh, WpTh, WpTl, 0, 0, 512,
        QKph, QKpl, 0, 0, 1024, 512, 3, 4, 0);

    // 3) V transposed, 2-term, single-fp16 out with row remap
    hgemm<<<dim3(128, 8, 1), 512, GEMM_SMEM>>>(
        WvnTh, WvnTl, nullptr, 0, 0, 512,
        Xnh, Xnh, nullptr, 0, 0, 512,
        Vth, nullptr, 0, 0, ROWS, 512, 2, 7, 0);
    hgemm<<<dim3(128, 8, 1), 512, GEMM_SMEM>>>(
        WvpTh, WvpTl, nullptr, 0, 0, 512,
        Xph, Xph, nullptr, 0, 0, 512,
        Vth, nullptr, 0, 0, ROWS, 512, 2, 7, 64);

    // 4) fused flash attention per softmax stream
    for (int s = 0; s < 2; s++) {
        const __half* Qh = s ? QKph : QKnh;
        const __half* Ql = s ? QKpl : QKnl;
        flash_attn<<<dim3(8, 128), 512, FA_SMEM>>>(
            Qh, Ql, Vth + (size_t)s * 16777216,
            Hnh + s * 64, Hnl + s * 64, Hph + s * 64, Hpl + s * 64);
    }

    // 5) output projections, 2-term, fp32 out
    hgemm<<<dim3(4, 128, 1), 512, GEMM_SMEM>>>(
        Hnh, Hnl, nullptr, 0, 0, 1024,
        WonTh, WonTh, nullptr, 0, 0, 1024,
        out, nullptr, 0, 0, 512, 1024, 2, 1, 0);
    hgemm<<<dim3(4, 128, 1), 512, GEMM_SMEM>>>(
        Hph, Hpl, nullptr, 0, 0, 1024,
        WopTh, WopTh, nullptr, 0, 0, 1024,
        out + (size_t)ROWS * 512, nullptr, 0, 0, 512, 1024, 2, 1, 0);
}

// round 7
// speedup vs baseline: 4.2864x; 1.2057x over previous
#include <cuda_runtime.h>
#include <cuda_fp16.h>

// ===========================================================================
// B=16, N=1024, D=512, H=8, dk=64. ROWS=16384.
// HMMA (mma.sync m16n8k16), fp32 accum, split-fp16 where precision needs it:
//   QK proj: 3-term (Xh*Wh + Xl*Wh + Xh*Wl), pair out (Q needs hi+lo)
//   S      : 2-term (Qh*Kh + Ql*Kh), K single-fp16
//   V proj : 1-term, out proj: 1-term, H single-fp16, PV: V-hi only
// ===========================================================================
#define ROWS 16384
#define PADK 72
#define TILEB (128 * PADK * 2)
#define GEMM_SMEM (4 * TILEB)

// Fused attention smem layout (bytes)
#define NKT   16
#define OFF_Q  0                    // Qhi 18432 + Qlo 18432
#define OFF_KV 36864                // 2 bufs x (Khi 9216 | V 18432)
#define KVBUF  27648
#define OFF_S  92160                // 128*66*4 fp32
#define OFF_P  125952               // 128*72*2 fp16
#define OFF_M  144384               // 128 fp32 row-max
#define OFF_L  144896               // 128 fp32 row-sum
#define OFF_F  145408               // 128 fp32 rescale
#define FA_SMEM 145920

// ---------------------------------------------------------------------------
// Static device scratch
// ---------------------------------------------------------------------------
__device__ __half g_WnTh [1024 * 512], g_WnTl [1024 * 512];
__device__ __half g_WpTh [1024 * 512], g_WpTl [1024 * 512];
__device__ __half g_WvnTh[1024 * 512];
__device__ __half g_WvpTh[1024 * 512];
__device__ __half g_WonTh[512 * 1024];
__device__ __half g_WopTh[512 * 1024];
__device__ __half g_Xnh[(size_t)ROWS * 512], g_Xnl[(size_t)ROWS * 512];
__device__ __half g_Xph[(size_t)ROWS * 512], g_Xpl[(size_t)ROWS * 512];
__device__ __half g_QKnh[(size_t)ROWS * 1024], g_QKnl[(size_t)ROWS * 1024];
__device__ __half g_QKph[(size_t)ROWS * 1024], g_QKpl[(size_t)ROWS * 1024];
__device__ __half g_Vth[(size_t)2048 * ROWS];
__device__ __half g_Hn [(size_t)ROWS * 1024];
__device__ __half g_Hp [(size_t)ROWS * 1024];

// ---------------------------------------------------------------------------
// PTX helpers
// ---------------------------------------------------------------------------
__device__ __forceinline__ unsigned smem_u32(const void* p) {
    unsigned a;
    asm("{ .reg .u64 t; cvta.to.shared.u64 t, %1; cvt.u32.u64 %0, t; }"
        : "=r"(a) : "l"(p));
    return a;
}
__device__ __forceinline__ void cpasync16(unsigned s, const void* g) {
    asm volatile("cp.async.cg.shared.global [%0], [%1], 16;" :: "r"(s), "l"(g));
}
__device__ __forceinline__ void cp_commit() {
    asm volatile("cp.async.commit_group;" ::: "memory");
}
__device__ __forceinline__ void cp_wait0() {
    asm volatile("cp.async.wait_group 0;" ::: "memory");
}
__device__ __forceinline__ void ldm4(unsigned& r0, unsigned& r1, unsigned& r2,
                                     unsigned& r3, unsigned a) {
    asm volatile("ldmatrix.sync.aligned.m8n8.x4.shared.b16 {%0,%1,%2,%3}, [%4];"
                 : "=r"(r0), "=r"(r1), "=r"(r2), "=r"(r3) : "r"(a));
}
__device__ __forceinline__ void mma16816(float* c, const unsigned* a,
                                         const unsigned* b) {
    asm volatile(
        "mma.sync.aligned.m16n8k16.row.col.f32.f16.f16.f32 "
        "{%0,%1,%2,%3}, {%4,%5,%6,%7}, {%8,%9}, {%0,%1,%2,%3};"
        : "+f"(c[0]), "+f"(c[1]), "+f"(c[2]), "+f"(c[3])
        : "r"(a[0]), "r"(a[1]), "r"(a[2]), "r"(a[3]), "r"(b[0]), "r"(b[1]));
}
__device__ __forceinline__ void split2(float v0, float v1, __half2& hi, __half2& lo) {
    __half h0 = __float2half_rn(v0), h1 = __float2half_rn(v1);
    __half l0 = __float2half_rn(v0 - __half2float(h0));
    __half l1 = __float2half_rn(v1 - __half2float(h1));
    hi = __halves2half2(h0, h1);
    lo = __halves2half2(l0, l1);
}

// ---------------------------------------------------------------------------
// Multi-term HMMA GEMM: C = sum_t At(M,K)*Bt(N,K)^T, fp16 in, fp32 accum.
// modes: 1 fp32 out | 4 fp16 pair out | 7 fp16 single out + V row remap
// ---------------------------------------------------------------------------
__global__ __launch_bounds__(512)
void hgemm(const __half* __restrict__ A0, const __half* __restrict__ A1,
           const __half* __restrict__ A2,
           long long sAh, long long sAb, int lda,
           const __half* __restrict__ B0, const __half* __restrict__ B1,
           const __half* __restrict__ B2,
           long long sBh, long long sBb, int ldb,
           void* __restrict__ C0, void* __restrict__ C1,
           long long sCh, long long sCb, int ldc,
           int Kper, int nterm, int mode, int halfoff) {
    extern __shared__ __align__(16) char smem[];
    const unsigned smA = smem_u32(smem);
    const unsigned smB = smA + 2 * TILEB;

    const int tid = threadIdx.x;
    const int wid = tid >> 5, lane = tid & 31;
    const int wm = wid & 3, wn = wid >> 2;

    const int zh = (int)(blockIdx.z >> 4), zb = (int)(blockIdx.z & 15);
    const long long aoff = sAh * zh + sAb * zb + (long long)(blockIdx.y * 128) * lda;
    const long long boff = sBh * zh + sBb * zb + (long long)(blockIdx.x * 128) * ldb;
    const __half* At[3] = {A0 + aoff, A1 ? A1 + aoff : A0, A2 ? A2 + aoff : A0};
    const __half* Bt[3] = {B0 + boff, B1 ? B1 + boff : B0, B2 ? B2 + boff : B0};

    const int r0c = tid >> 3, s0c = tid & 7;
    const int r1c = r0c + 64;
    const int trA0 = r0c * lda + s0c * 8, trA1 = r1c * lda + s0c * 8;
    const int trB0 = r0c * ldb + s0c * 8, trB1 = r1c * ldb + s0c * 8;
    const unsigned so0 = (unsigned)(r0c * PADK + s0c * 8) * 2;
    const unsigned so1 = (unsigned)(r1c * PADK + s0c * 8) * 2;

    const int T = Kper >> 6;
    const int TT = nterm * T;

#define LOAD_TILE(g, bf)                                                      \
    do {                                                                      \
        int t_ = ((g) >= T) + ((g) >= 2 * T);                                 \
        int kk_ = (g) - t_ * T;                                               \
        const __half* ap = At[t_] + kk_ * 64;                                 \
        const __half* bp = Bt[t_] + kk_ * 64;                                 \
        cpasync16(smA + (bf) * TILEB + so0, ap + trA0);                       \
        cpasync16(smA + (bf) * TILEB + so1, ap + trA1);                       \
        cpasync16(smB + (bf) * TILEB + so0, bp + trB0);                       \
        cpasync16(smB + (bf) * TILEB + so1, bp + trB1);                       \
        cp_commit();                                                          \
    } while (0)

    LOAD_TILE(0, 0);

    float acc[2][4][4];
#pragma unroll
    for (int i = 0; i < 2; i++)
#pragma unroll
        for (int j = 0; j < 4; j++)
#pragma unroll
            for (int k = 0; k < 4; k++) acc[i][j][k] = 0.f;

    const int sub = lane >> 3, r8 = lane & 7;

    for (int g = 0; g < TT; g++) {
        const int bf = g & 1;
        cp_wait0();
        __syncthreads();
        if (g + 1 < TT) LOAD_TILE(g + 1, bf ^ 1);

        const unsigned ab = smA + bf * TILEB;
        const unsigned bb = smB + bf * TILEB;
#pragma unroll
        for (int ks = 0; ks < 4; ks++) {
            const int k0 = ks * 16;
            unsigned a[2][4];
#pragma unroll
            for (int mi = 0; mi < 2; mi++) {
                int mrow = wm * 32 + mi * 16 + r8 + (sub & 1) * 8;
                int mcol = k0 + (sub >> 1) * 8;
                ldm4(a[mi][0], a[mi][1], a[mi][2], a[mi][3],
                     ab + (unsigned)(mrow * PADK + mcol) * 2);
            }
            unsigned b[4][2];
#pragma unroll
            for (int np = 0; np < 2; np++) {
                int nrow = wn * 32 + np * 16 + r8 + (sub >> 1) * 8;
                int kcol = k0 + (sub & 1) * 8;
                unsigned q0, q1, q2, q3;
                ldm4(q0, q1, q2, q3, bb + (unsigned)(nrow * PADK + kcol) * 2);
                b[np * 2][0] = q0; b[np * 2][1] = q1;
                b[np * 2 + 1][0] = q2; b[np * 2 + 1][1] = q3;
            }
#pragma unroll
            for (int mi = 0; mi < 2; mi++)
#pragma unroll
                for (int ni = 0; ni < 4; ni++)
                    mma16816(acc[mi][ni], a[mi], b[ni]);
        }
        __syncthreads();
    }
#undef LOAD_TILE

    const int trow = lane >> 2, tcol = (lane & 3) * 2;
    const long long coff = sCh * zh + sCb * zb;

#pragma unroll
    for (int mi = 0; mi < 2; mi++) {
#pragma unroll
        for (int ni = 0; ni < 4; ni++) {
            int rg = blockIdx.y * 128 + wm * 32 + mi * 16 + trow;
            int cg = blockIdx.x * 128 + wn * 32 + ni * 8 + tcol;
            float* ac = acc[mi][ni];
            if (mode == 1) {
                float* p0 = (float*)C0 + coff + (size_t)rg * ldc + cg;
                float* p1 = (float*)C0 + coff + (size_t)(rg + 8) * ldc + cg;
                *(float2*)p0 = make_float2(ac[0], ac[1]);
                *(float2*)p1 = make_float2(ac[2], ac[3]);
            } else if (mode == 4) {
                __half2 h, l;
                size_t o0 = coff + (size_t)rg * ldc + cg;
                size_t o1 = coff + (size_t)(rg + 8) * ldc + cg;
                split2(ac[0], ac[1], h, l);
                *(__half2*)((__half*)C0 + o0) = h;
                *(__half2*)((__half*)C1 + o0) = l;
                split2(ac[2], ac[3], h, l);
                *(__half2*)((__half*)C0 + o1) = h;
                *(__half2*)((__half*)C1 + o1) = l;
            } else {  // mode 7: single fp16 out + V row remap
                int ra = ((rg >> 6) << 7) + (rg & 63) + halfoff;
                int rb0 = rg + 8;
                int rb = ((rb0 >> 6) << 7) + (rb0 & 63) + halfoff;
                *(__half2*)((__half*)C0 + coff + (size_t)ra * ldc + cg) =
                    __floats2half2_rn(ac[0], ac[1]);
                *(__half2*)((__half*)C0 + coff + (size_t)rb * ldc + cg) =
                    __floats2half2_rn(ac[2], ac[3]);
            }
        }
    }
}

// ---------------------------------------------------------------------------
// Fused flash attention. Block = 128 q-rows for one (stream, h, b).
// S = Qh*Kh^T + Ql*Kh^T (Q pre-scaled 1/8), online softmax, O += P * Vh^T.
// Output: single fp16 into Hn (cols<64) / Hp (cols>=64).
// ---------------------------------------------------------------------------
__global__ __launch_bounds__(512)
void flash_attn(const __half* __restrict__ QKh, const __half* __restrict__ QKl,
                const __half* __restrict__ Vh,
                __half* __restrict__ C0, __half* __restrict__ C1) {
    extern __shared__ __align__(16) char smem[];
    const unsigned sb = smem_u32(smem);
    float* Sf  = (float*)(smem + OFF_S);
    __half* Pm = (__half*)(smem + OFF_P);
    float* smM = (float*)(smem + OFF_M);
    float* smL = (float*)(smem + OFF_L);
    float* smF = (float*)(smem + OFF_F);

    const int tid = threadIdx.x, wid = tid >> 5, lane = tid & 31;
    const int wm = wid & 3, wn = wid >> 2;
    const int sub = lane >> 3, r8 = lane & 7;
    const int trow = lane >> 2, tcol = (lane & 3) * 2;
    const int qt = blockIdx.x, z = blockIdx.y;
    const int h = z >> 4, b = z & 15;

    if (tid < 128) { smM[tid] = -1e30f; smL[tid] = 0.f; }

    {
        const size_t rbase = (size_t)(b << 10) + qt * 128;
        int c0 = tid, c1 = tid + 512;
        int r0 = c0 >> 3, s0 = c0 & 7, r1 = c1 >> 3, s1 = c1 & 7;
        int col0 = h * 64 + s0 * 8, col1 = h * 64 + s1 * 8;
        cpasync16(sb + OFF_Q + (unsigned)(r0 * 72 + s0 * 8) * 2,
                  QKh + (rbase + r0) * 1024 + col0);
        cpasync16(sb + OFF_Q + (unsigned)(r1 * 72 + s1 * 8) * 2,
                  QKh + (rbase + r1) * 1024 + col1);
        cpasync16(sb + OFF_Q + 18432 + (unsigned)(r0 * 72 + s0 * 8) * 2,
                  QKl + (rbase + r0) * 1024 + col0);
        cpasync16(sb + OFF_Q + 18432 + (unsigned)(r1 * 72 + s1 * 8) * 2,
                  QKl + (rbase + r1) * 1024 + col1);
    }

#define LOAD_KV(kt, bi)                                                       \
    do {                                                                      \
        int rr = tid >> 3, ss = tid & 7;                                      \
        size_t gr = (size_t)(b << 10) + (kt) * 64 + rr;                       \
        unsigned sof = (unsigned)(rr * 72 + ss * 8) * 2;                      \
        cpasync16(sb + OFF_KV + (bi) * KVBUF + sof,                           \
                  QKh + gr * 1024 + 512 + h * 64 + ss * 8);                   \
        int v0 = tid, v1 = tid + 512;                                         \
        int vr0 = v0 >> 3, vs0 = v0 & 7, vr1 = v1 >> 3, vs1 = v1 & 7;         \
        size_t vcb = (size_t)(b << 10) + (kt) * 64;                           \
        cpasync16(sb + OFF_KV + (bi) * KVBUF + 9216 +                         \
                      (unsigned)(vr0 * 72 + vs0 * 8) * 2,                     \
                  Vh + (size_t)(h * 128 + vr0) * 16384 + vcb + vs0 * 8);      \
        cpasync16(sb + OFF_KV + (bi) * KVBUF + 9216 +                         \
                      (unsigned)(vr1 * 72 + vs1 * 8) * 2,                     \
                  Vh + (size_t)(h * 128 + vr1) * 16384 + vcb + vs1 * 8);      \
        cp_commit();                                                          \
    } while (0)

    LOAD_KV(0, 0);
    cp_wait0();

    float O[2][4][4] = {};

    for (int kt = 0; kt < NKT; kt++) {
        const int bi = kt & 1;
        if (kt) cp_wait0();
        __syncthreads();
        if (kt + 1 < NKT) LOAD_KV(kt + 1, bi ^ 1);

        const unsigned Kh = sb + OFF_KV + bi * KVBUF;
        const unsigned Vb = Kh + 9216;

        // ---- S phase: 2 terms (Qh*Kh + Ql*Kh) ----
        float acc[2][2][4] = {};
#pragma unroll
        for (int ks = 0; ks < 4; ks++) {
            const int k0 = ks * 16;
            unsigned ah[2][4], al[2][4];
#pragma unroll
            for (int mi = 0; mi < 2; mi++) {
                unsigned off = (unsigned)((wm * 32 + mi * 16 + r8 + (sub & 1) * 8) * 72 +
                                          k0 + (sub >> 1) * 8) * 2;
                ldm4(ah[mi][0], ah[mi][1], ah[mi][2], ah[mi][3], sb + OFF_Q + off);
                ldm4(al[mi][0], al[mi][1], al[mi][2], al[mi][3],
                     sb + OFF_Q + 18432 + off);
            }
            unsigned bh[2][2];
            {
                unsigned off = (unsigned)((wn * 16 + r8 + (sub >> 1) * 8) * 72 +
                                          k0 + (sub & 1) * 8) * 2;
                unsigned q0, q1, q2, q3;
                ldm4(q0, q1, q2, q3, Kh + off);
                bh[0][0] = q0; bh[0][1] = q1; bh[1][0] = q2; bh[1][1] = q3;
            }
#pragma unroll
            for (int mi = 0; mi < 2; mi++)
#pragma unroll
                for (int nf = 0; nf < 2; nf++) {
                    mma16816(acc[mi][nf], ah[mi], bh[nf]);
                    mma16816(acc[mi][nf], al[mi], bh[nf]);
                }
        }
#pragma unroll
        for (int mi = 0; mi < 2; mi++)
#pragma unroll
            for (int nf = 0; nf < 2; nf++) {
                int r0 = wm * 32 + mi * 16 + trow;
                int col = wn * 16 + nf * 8 + tcol;
                *(float2*)&Sf[r0 * 66 + col] =
                    make_float2(acc[mi][nf][0], acc[mi][nf][1]);
                *(float2*)&Sf[(r0 + 8) * 66 + col] =
                    make_float2(acc[mi][nf][2], acc[mi][nf][3]);
            }
        __syncthreads();

        // ---- online softmax ----
        {
            int r = tid >> 2, seg = tid & 3;
            float vals[16];
            float* bp = &Sf[r * 66 + seg * 16];
#pragma unroll
            for (int i = 0; i < 8; i++) {
                float2 t2 = *(float2*)(bp + 2 * i);
                vals[2 * i] = t2.x; vals[2 * i + 1] = t2.y;
            }
            float mt = vals[0];
#pragma unroll
            for (int i = 1; i < 16; i++) mt = fmaxf(mt, vals[i]);
            mt = fmaxf(mt, __shfl_xor_sync(~0u, mt, 1));
            mt = fmaxf(mt, __shfl_xor_sync(~0u, mt, 2));
            float mo = smM[r];
            float mn = fmaxf(mo, mt);
            float f = __expf(mo - mn);
            float sum = 0.f;
            __half* pp = &Pm[r * 72 + seg * 16];
#pragma unroll
            for (int i = 0; i < 8; i++) {
                float e0 = __expf(vals[2 * i] - mn);
                float e1 = __expf(vals[2 * i + 1] - mn);
                *(__half2*)(pp + 2 * i) = __floats2half2_rn(e0, e1);
                sum += e0 + e1;
            }
            sum += __shfl_xor_sync(~0u, sum, 1);
            sum += __shfl_xor_sync(~0u, sum, 2);
            if (seg == 0) {
                smM[r] = mn;
                smL[r] = smL[r] * f + sum;
                smF[r] = f;
            }
        }
        __syncthreads();

        // ---- PV phase ----
#pragma unroll
        for (int mi = 0; mi < 2; mi++) {
            float f0 = smF[wm * 32 + mi * 16 + trow];
            float f1 = smF[wm * 32 + mi * 16 + trow + 8];
#pragma unroll
            for (int nf = 0; nf < 4; nf++) {
                O[mi][nf][0] *= f0; O[mi][nf][1] *= f0;
                O[mi][nf][2] *= f1; O[mi][nf][3] *= f1;
            }
        }
#pragma unroll
        for (int ks = 0; ks < 4; ks++) {
            const int k0 = ks * 16;
            unsigned aP[2][4];
#pragma unroll
            for (int mi = 0; mi < 2; mi++) {
                unsigned off = (unsigned)((wm * 32 + mi * 16 + r8 + (sub & 1) * 8) * 72 +
                                          k0 + (sub >> 1) * 8) * 2;
                ldm4(aP[mi][0], aP[mi][1], aP[mi][2], aP[mi][3], sb + OFF_P + off);
            }
            unsigned bV[4][2];
#pragma unroll
            for (int np = 0; np < 2; np++) {
                unsigned off = (unsigned)((wn * 32 + np * 16 + r8 + (sub >> 1) * 8) * 72 +
                                          k0 + (sub & 1) * 8) * 2;
                unsigned q0, q1, q2, q3;
                ldm4(q0, q1, q2, q3, Vb + off);
                bV[np * 2][0] = q0; bV[np * 2][1] = q1;
                bV[np * 2 + 1][0] = q2; bV[np * 2 + 1][1] = q3;
            }
#pragma unroll
            for (int mi = 0; mi < 2; mi++)
#pragma unroll
                for (int nf = 0; nf < 4; nf++)
                    mma16816(O[mi][nf], aP[mi], bV[nf]);
        }
    }
#undef LOAD_KV

    // ---- epilogue: normalize, single fp16 out, split node/pos cols ----
    const long long coff = 128LL * h + 1048576LL * b;
#pragma unroll
    for (int mi = 0; mi < 2; mi++) {
        int r0 = wm * 32 + mi * 16 + trow;
        float inv0 = 1.f / smL[r0], inv1 = 1.f / smL[r0 + 8];
        int rg0 = qt * 128 + r0, rg1 = rg0 + 8;
#pragma unroll
        for (int nf = 0; nf < 4; nf++) {
            int cg = wn * 32 + nf * 8 + tcol;
            __half* base = (cg < 64) ? C0 : C1;
            int cl = cg & 63;
            *(__half2*)(base + coff + (size_t)rg0 * 1024 + cl) =
                __floats2half2_rn(O[mi][nf][0] * inv0, O[mi][nf][1] * inv0);
            *(__half2*)(base + coff + (size_t)rg1 * 1024 + cl) =
                __floats2half2_rn(O[mi][nf][2] * inv1, O[mi][nf][3] * inv1);
        }
    }
}

// ---------------------------------------------------------------------------
// Prep kernels
// ---------------------------------------------------------------------------
__global__ void cvt_pair(const float* __restrict__ X, __half* __restrict__ Yh,
                         __half* __restrict__ Yl, int n4) {
    int i = blockIdx.x * blockDim.x + threadIdx.x;
    if (i >= n4) return;
    float4 v = ((const float4*)X)[i];
    __half2 h0, l0, h1, l1;
    split2(v.x, v.y, h0, l0);
    split2(v.z, v.w, h1, l1);
    uint2 uh, ul;
    uh.x = *reinterpret_cast<unsigned*>(&h0);
    uh.y = *reinterpret_cast<unsigned*>(&h1);
    ul.x = *reinterpret_cast<unsigned*>(&l0);
    ul.y = *reinterpret_cast<unsigned*>(&l1);
    ((uint2*)Yh)[i] = uh;
    ((uint2*)Yl)[i] = ul;
}

__global__ void repack_qk(const float* __restrict__ Wq, const float* __restrict__ Wk,
                          __half* __restrict__ WTh, __half* __restrict__ WTl) {
    int idx = blockIdx.x * blockDim.x + threadIdx.x;
    if (idx >= 1024 * 512) return;
    int j = idx >> 9, d = idx & 511;
    int jj = j & 511;
    float v;
    if (j < 512)
        v = Wq[((size_t)((jj >> 6) * 512 + d)) * 64 + (jj & 63)] * 0.125f;
    else
        v = Wk[((size_t)((jj >> 6) * 512 + d)) * 64 + (jj & 63)];
    __half h = __float2half_rn(v);
    WTh[idx] = h;
    WTl[idx] = __float2half_rn(v - __half2float(h));
}

__global__ void repack_v(const float* __restrict__ Wv, __half* __restrict__ WTh) {
    int idx = blockIdx.x * blockDim.x + threadIdx.x;
    if (idx >= 1024 * 512) return;
    int j = idx >> 9, d = idx & 511;
    WTh[idx] = __float2half_rn(Wv[((size_t)((j >> 6) * 512 + d)) * 64 + (j & 63)]);
}

__global__ void repack_wo(const float* __restrict__ Wo, __half* __restrict__ WTh) {
    int idx = blockIdx.x * blockDim.x + threadIdx.x;
    if (idx >= 512 * 1024) return;
    int e = idx >> 10, j = idx & 1023;
    WTh[idx] = __float2half_rn(Wo[(size_t)j * 512 + e]);
}

// ---------------------------------------------------------------------------
// Host launcher
// ---------------------------------------------------------------------------
extern "C" void kernel_launch(void* const* d_in, const int* in_sizes, int n_in,
                              void* d_out, int out_size) {
    const float* Xn  = (const float*)d_in[0];
    const float* Xp  = (const float*)d_in[1];
    const float* Wqn = (const float*)d_in[2];
    const float* Wqp = (const float*)d_in[3];
    const float* Wkn = (const float*)d_in[4];
    const float* Wkp = (const float*)d_in[5];
    const float* Wvn = (const float*)d_in[6];
    const float* Wvp = (const float*)d_in[7];
    const float* Won = (const float*)d_in[8];
    const float* Wop = (const float*)d_in[9];
    float* out = (float*)d_out;

    __half *WnTh, *WnTl, *WpTh, *WpTl, *WvnTh, *WvpTh, *WonTh, *WopTh;
    __half *Xnh, *Xnl, *Xph, *Xpl, *QKnh, *QKnl, *QKph, *QKpl;
    __half *Vth, *Hn, *Hp;
    cudaGetSymbolAddress((void**)&WnTh,  g_WnTh);
    cudaGetSymbolAddress((void**)&WnTl,  g_WnTl);
    cudaGetSymbolAddress((void**)&WpTh,  g_WpTh);
    cudaGetSymbolAddress((void**)&WpTl,  g_WpTl);
    cudaGetSymbolAddress((void**)&WvnTh, g_WvnTh);
    cudaGetSymbolAddress((void**)&WvpTh, g_WvpTh);
    cudaGetSymbolAddress((void**)&WonTh, g_WonTh);
    cudaGetSymbolAddress((void**)&WopTh, g_WopTh);
    cudaGetSymbolAddress((void**)&Xnh,   g_Xnh);
    cudaGetSymbolAddress((void**)&Xnl,   g_Xnl);
    cudaGetSymbolAddress((void**)&Xph,   g_Xph);
    cudaGetSymbolAddress((void**)&Xpl,   g_Xpl);
    cudaGetSymbolAddress((void**)&QKnh,  g_QKnh);
    cudaGetSymbolAddress((void**)&QKnl,  g_QKnl);
    cudaGetSymbolAddress((void**)&QKph,  g_QKph);
    cudaGetSymbolAddress((void**)&QKpl,  g_QKpl);
    cudaGetSymbolAddress((void**)&Vth,   g_Vth);
    cudaGetSymbolAddress((void**)&Hn,    g_Hn);
    cudaGetSymbolAddress((void**)&Hp,    g_Hp);

    cudaFuncSetAttribute(hgemm, cudaFuncAttributeMaxDynamicSharedMemorySize,
                         GEMM_SMEM);
    cudaFuncSetAttribute(flash_attn, cudaFuncAttributeMaxDynamicSharedMemorySize,
                         FA_SMEM);

    // 1) repacks + conversions
    repack_qk<<<2048, 256>>>(Wqn, Wkn, WnTh, WnTl);
    repack_qk<<<2048, 256>>>(Wqp, Wkp, WpTh, WpTl);
    repack_v <<<2048, 256>>>(Wvn, WvnTh);
    repack_v <<<2048, 256>>>(Wvp, WvpTh);
    repack_wo<<<2048, 256>>>(Won, WonTh);
    repack_wo<<<2048, 256>>>(Wop, WopTh);
    cvt_pair<<<8192, 256>>>(Xn, Xnh, Xnl, ROWS * 512 / 4);
    cvt_pair<<<8192, 256>>>(Xp, Xph, Xpl, ROWS * 512 / 4);

    // 2) Q,K projections, 3-term, pair out
    hgemm<<<dim3(8, 128, 1), 512, GEMM_SMEM>>>(
        Xnh, Xnl, Xnh, 0, 0, 512,
        WnTh, WnTh, WnTl, 0, 0, 512,
        QKnh, QKnl, 0, 0, 1024, 512, 3, 4, 0);
    hgemm<<<dim3(8, 128, 1), 512, GEMM_SMEM>>>(
        Xph, Xpl, Xph, 0, 0, 512,
        WpTh, WpTh, WpTl, 0, 0, 512,
        QKph, QKpl, 0, 0, 1024, 512, 3, 4, 0);

    // 3) V transposed, 1-term, single-fp16 out with row remap
    hgemm<<<dim3(128, 8, 1), 512, GEMM_SMEM>>>(
        WvnTh, nullptr, nullptr, 0, 0, 512,
        Xnh, nullptr, nullptr, 0, 0, 512,
        Vth, nullptr, 0, 0, ROWS, 512, 1, 7, 0);
    hgemm<<<dim3(128, 8, 1), 512, GEMM_SMEM>>>(
        WvpTh, nullptr, nullptr, 0, 0, 512,
        Xph, nullptr, nullptr, 0, 0, 512,
        Vth, nullptr, 0, 0, ROWS, 512, 1, 7, 64);

    // 4) fused flash attention per softmax stream
    for (int s = 0; s < 2; s++) {
        const __half* Qh = s ? QKph : QKnh;
        const __half* Ql = s ? QKpl : QKnl;
        flash_attn<<<dim3(8, 128), 512, FA_SMEM>>>(
            Qh, Ql, Vth + (size_t)s * 16777216,
            Hn + s * 64, Hp + s * 64);
    }

    // 5) output projections, 1-term, fp32 out
    hgemm<<<dim3(4, 128, 1), 512, GEMM_SMEM>>>(
        Hn, nullptr, nullptr, 0, 0, 1024,
        WonTh, nullptr, nullptr, 0, 0, 1024,
        out, nullptr, 0, 0, 512, 1024, 1, 1, 0);
    hgemm<<<dim3(4, 128, 1), 512, GEMM_SMEM>>>(
        Hp, nullptr, nullptr, 0, 0, 1024,
        WopTh, nullptr, nullptr, 0, 0, 1024,
        out + (size_t)ROWS * 512, nullptr, 0, 0, 512, 1024, 1, 1, 0);
}

// round 8
// speedup vs baseline: 4.4636x; 1.0413x over previous
#include <cuda_runtime.h>
#include <cuda_fp16.h>

// ===========================================================================
// B=16, N=1024, D=512, H=8, dk=64. ROWS=16384.
// HMMA (mma.sync m16n8k16), fp32 accum, split-fp16 where precision needs it:
//   QK proj: 3-term (Xh*Wh + Xl*Wh + Xh*Wl), pair out
//   S      : 2-term (Qh*Kh + Ql*Kh), online softmax in fused flash kernel
//   V proj : 1-term, out proj: 1-term, PV: V-hi only
// All node/pos pairs merged into single launches via 2-stream arrays.
// ===========================================================================
#define ROWS 16384
#define PADK 72
#define TILEB (128 * PADK * 2)
#define GEMM_SMEM (4 * TILEB)

#define XSTR  ((long long)ROWS * 512)       // 8388608
#define WSTR  (524288LL)
#define QKSTR ((long long)ROWS * 1024)      // 16777216
#define HSTR  ((long long)ROWS * 1024)
#define OSTR  ((long long)ROWS * 512)       // fp32 elements

// Fused attention smem layout (bytes)
#define NKT   16
#define OFF_Q  0                    // Qhi 18432 + Qlo 18432
#define OFF_KV 36864                // 2 bufs x (Khi 9216 | V 18432)
#define KVBUF  27648
#define OFF_S  92160                // 128*66*4 fp32
#define OFF_P  125952               // 128*72*2 fp16
#define OFF_M  144384
#define OFF_L  144896
#define OFF_F  145408
#define FA_SMEM 145920

// ---------------------------------------------------------------------------
// Static device scratch (2-stream arrays: stride between streams guaranteed)
// ---------------------------------------------------------------------------
__device__ __half g_Wqkh[2][524288], g_Wqkl[2][524288];
__device__ __half g_Wvh [2][524288];
__device__ __half g_Woh [2][524288];
__device__ __half g_Xh  [2][8388608], g_Xl[2][8388608];
__device__ __half g_QKh [2][16777216], g_QKl[2][16777216];
__device__ __half g_Vth [2][16777216];
__device__ __half g_H   [2][16777216];

// ---------------------------------------------------------------------------
// PTX helpers
// ---------------------------------------------------------------------------
__device__ __forceinline__ unsigned smem_u32(const void* p) {
    unsigned a;
    asm("{ .reg .u64 t; cvta.to.shared.u64 t, %1; cvt.u32.u64 %0, t; }"
        : "=r"(a) : "l"(p));
    return a;
}
__device__ __forceinline__ void cpasync16(unsigned s, const void* g) {
    asm volatile("cp.async.cg.shared.global [%0], [%1], 16;" :: "r"(s), "l"(g));
}
__device__ __forceinline__ void cp_commit() {
    asm volatile("cp.async.commit_group;" ::: "memory");
}
__device__ __forceinline__ void cp_wait0() {
    asm volatile("cp.async.wait_group 0;" ::: "memory");
}
__device__ __forceinline__ void ldm4(unsigned& r0, unsigned& r1, unsigned& r2,
                                     unsigned& r3, unsigned a) {
    asm volatile("ldmatrix.sync.aligned.m8n8.x4.shared.b16 {%0,%1,%2,%3}, [%4];"
                 : "=r"(r0), "=r"(r1), "=r"(r2), "=r"(r3) : "r"(a));
}
__device__ __forceinline__ void mma16816(float* c, const unsigned* a,
                                         const unsigned* b) {
    asm volatile(
        "mma.sync.aligned.m16n8k16.row.col.f32.f16.f16.f32 "
        "{%0,%1,%2,%3}, {%4,%5,%6,%7}, {%8,%9}, {%0,%1,%2,%3};"
        : "+f"(c[0]), "+f"(c[1]), "+f"(c[2]), "+f"(c[3])
        : "r"(a[0]), "r"(a[1]), "r"(a[2]), "r"(a[3]), "r"(b[0]), "r"(b[1]));
}
__device__ __forceinline__ void split2(float v0, float v1, __half2& hi, __half2& lo) {
    __half h0 = __float2half_rn(v0), h1 = __float2half_rn(v1);
    __half l0 = __float2half_rn(v0 - __half2float(h0));
    __half l1 = __float2half_rn(v1 - __half2float(h1));
    hi = __halves2half2(h0, h1);
    lo = __halves2half2(l0, l1);
}

// ---------------------------------------------------------------------------
// Multi-term HMMA GEMM: C = sum_t At(M,K)*Bt(N,K)^T, fp16 in, fp32 accum.
// blockIdx.z -> zb (stream) with per-operand strides sAb/sBb/sCb.
// modes: 1 fp32 out | 4 fp16 pair out | 7 fp16 single out + V row remap,
//        remap half offset = halfoff * zb.
// ---------------------------------------------------------------------------
__global__ __launch_bounds__(512)
void hgemm(const __half* __restrict__ A0, const __half* __restrict__ A1,
           const __half* __restrict__ A2,
           long long sAh, long long sAb, int lda,
           const __half* __restrict__ B0, const __half* __restrict__ B1,
           const __half* __restrict__ B2,
           long long sBh, long long sBb, int ldb,
           void* __restrict__ C0, void* __restrict__ C1,
           long long sCh, long long sCb, int ldc,
           int Kper, int nterm, int mode, int halfoff) {
    extern __shared__ __align__(16) char smem[];
    const unsigned smA = smem_u32(smem);
    const unsigned smB = smA + 2 * TILEB;

    const int tid = threadIdx.x;
    const int wid = tid >> 5, lane = tid & 31;
    const int wm = wid & 3, wn = wid >> 2;

    const int zh = (int)(blockIdx.z >> 4), zb = (int)(blockIdx.z & 15);
    const long long aoff = sAh * zh + sAb * zb + (long long)(blockIdx.y * 128) * lda;
    const long long boff = sBh * zh + sBb * zb + (long long)(blockIdx.x * 128) * ldb;
    const __half* At[3] = {A0 + aoff, A1 ? A1 + aoff : A0, A2 ? A2 + aoff : A0};
    const __half* Bt[3] = {B0 + boff, B1 ? B1 + boff : B0, B2 ? B2 + boff : B0};

    const int r0c = tid >> 3, s0c = tid & 7;
    const int r1c = r0c + 64;
    const int trA0 = r0c * lda + s0c * 8, trA1 = r1c * lda + s0c * 8;
    const int trB0 = r0c * ldb + s0c * 8, trB1 = r1c * ldb + s0c * 8;
    const unsigned so0 = (unsigned)(r0c * PADK + s0c * 8) * 2;
    const unsigned so1 = (unsigned)(r1c * PADK + s0c * 8) * 2;

    const int T = Kper >> 6;
    const int TT = nterm * T;

#define LOAD_TILE(g, bf)                                                      \
    do {                                                                      \
        int t_ = ((g) >= T) + ((g) >= 2 * T);                                 \
        int kk_ = (g) - t_ * T;                                               \
        const __half* ap = At[t_] + kk_ * 64;                                 \
        const __half* bp = Bt[t_] + kk_ * 64;                                 \
        cpasync16(smA + (bf) * TILEB + so0, ap + trA0);                       \
        cpasync16(smA + (bf) * TILEB + so1, ap + trA1);                       \
        cpasync16(smB + (bf) * TILEB + so0, bp + trB0);                       \
        cpasync16(smB + (bf) * TILEB + so1, bp + trB1);                       \
        cp_commit();                                                          \
    } while (0)

    LOAD_TILE(0, 0);

    float acc[2][4][4];
#pragma unroll
    for (int i = 0; i < 2; i++)
#pragma unroll
        for (int j = 0; j < 4; j++)
#pragma unroll
            for (int k = 0; k < 4; k++) acc[i][j][k] = 0.f;

    const int sub = lane >> 3, r8 = lane & 7;

    for (int g = 0; g < TT; g++) {
        const int bf = g & 1;
        cp_wait0();
        __syncthreads();
        if (g + 1 < TT) LOAD_TILE(g + 1, bf ^ 1);

        const unsigned ab = smA + bf * TILEB;
        const unsigned bb = smB + bf * TILEB;
#pragma unroll
        for (int ks = 0; ks < 4; ks++) {
            const int k0 = ks * 16;
            unsigned a[2][4];
#pragma unroll
            for (int mi = 0; mi < 2; mi++) {
                int mrow = wm * 32 + mi * 16 + r8 + (sub & 1) * 8;
                int mcol = k0 + (sub >> 1) * 8;
                ldm4(a[mi][0], a[mi][1], a[mi][2], a[mi][3],
                     ab + (unsigned)(mrow * PADK + mcol) * 2);
            }
            unsigned b[4][2];
#pragma unroll
            for (int np = 0; np < 2; np++) {
                int nrow = wn * 32 + np * 16 + r8 + (sub >> 1) * 8;
                int kcol = k0 + (sub & 1) * 8;
                unsigned q0, q1, q2, q3;
                ldm4(q0, q1, q2, q3, bb + (unsigned)(nrow * PADK + kcol) * 2);
                b[np * 2][0] = q0; b[np * 2][1] = q1;
                b[np * 2 + 1][0] = q2; b[np * 2 + 1][1] = q3;
            }
#pragma unroll
            for (int mi = 0; mi < 2; mi++)
#pragma unroll
                for (int ni = 0; ni < 4; ni++)
                    mma16816(acc[mi][ni], a[mi], b[ni]);
        }
        __syncthreads();
    }
#undef LOAD_TILE

    const int trow = lane >> 2, tcol = (lane & 3) * 2;
    const long long coff = sCh * zh + sCb * zb;

#pragma unroll
    for (int mi = 0; mi < 2; mi++) {
#pragma unroll
        for (int ni = 0; ni < 4; ni++) {
            int rg = blockIdx.y * 128 + wm * 32 + mi * 16 + trow;
            int cg = blockIdx.x * 128 + wn * 32 + ni * 8 + tcol;
            float* ac = acc[mi][ni];
            if (mode == 1) {
                float* p0 = (float*)C0 + coff + (size_t)rg * ldc + cg;
                float* p1 = (float*)C0 + coff + (size_t)(rg + 8) * ldc + cg;
                *(float2*)p0 = make_float2(ac[0], ac[1]);
                *(float2*)p1 = make_float2(ac[2], ac[3]);
            } else if (mode == 4) {
                __half2 h, l;
                size_t o0 = coff + (size_t)rg * ldc + cg;
                size_t o1 = coff + (size_t)(rg + 8) * ldc + cg;
                split2(ac[0], ac[1], h, l);
                *(__half2*)((__half*)C0 + o0) = h;
                *(__half2*)((__half*)C1 + o0) = l;
                split2(ac[2], ac[3], h, l);
                *(__half2*)((__half*)C0 + o1) = h;
                *(__half2*)((__half*)C1 + o1) = l;
            } else {  // mode 7: single fp16 out + V row remap (halfoff * zb)
                int ho = halfoff * zb;
                int ra = ((rg >> 6) << 7) + (rg & 63) + ho;
                int rb0 = rg + 8;
                int rb = ((rb0 >> 6) << 7) + (rb0 & 63) + ho;
                *(__half2*)((__half*)C0 + (size_t)ra * ldc + cg) =
                    __floats2half2_rn(ac[0], ac[1]);
                *(__half2*)((__half*)C0 + (size_t)rb * ldc + cg) =
                    __floats2half2_rn(ac[2], ac[3]);
            }
        }
    }
}

// ---------------------------------------------------------------------------
// Fused flash attention, both softmax streams in one launch (blockIdx.z).
// S = Qh*Kh^T + Ql*Kh^T (Q pre-scaled 1/8), online softmax, O += P * Vh^T.
// ---------------------------------------------------------------------------
__global__ __launch_bounds__(512)
void flash_attn(const __half* __restrict__ QKhB, const __half* __restrict__ QKlB,
                const __half* __restrict__ VhB,
                __half* __restrict__ H0B, __half* __restrict__ H1B) {
    extern __shared__ __align__(16) char smem[];
    const unsigned sb = smem_u32(smem);
    float* Sf  = (float*)(smem + OFF_S);
    __half* Pm = (__half*)(smem + OFF_P);
    float* smM = (float*)(smem + OFF_M);
    float* smL = (float*)(smem + OFF_L);
    float* smF = (float*)(smem + OFF_F);

    const int tid = threadIdx.x, wid = tid >> 5, lane = tid & 31;
    const int wm = wid & 3, wn = wid >> 2;
    const int sub = lane >> 3, r8 = lane & 7;
    const int trow = lane >> 2, tcol = (lane & 3) * 2;
    const int qt = blockIdx.x, z = blockIdx.y;
    const int h = z >> 4, b = z & 15;
    const int s = blockIdx.z;

    const __half* QKh = QKhB + (size_t)s * QKSTR;
    const __half* QKl = QKlB + (size_t)s * QKSTR;
    const __half* Vh  = VhB  + (size_t)s * 16777216;
    __half* C0 = H0B + s * 64;
    __half* C1 = H1B + s * 64;

    if (tid < 128) { smM[tid] = -1e30f; smL[tid] = 0.f; }

    {
        const size_t rbase = (size_t)(b << 10) + qt * 128;
        int c0 = tid, c1 = tid + 512;
        int r0 = c0 >> 3, s0 = c0 & 7, r1 = c1 >> 3, s1 = c1 & 7;
        int col0 = h * 64 + s0 * 8, col1 = h * 64 + s1 * 8;
        cpasync16(sb + OFF_Q + (unsigned)(r0 * 72 + s0 * 8) * 2,
                  QKh + (rbase + r0) * 1024 + col0);
        cpasync16(sb + OFF_Q + (unsigned)(r1 * 72 + s1 * 8) * 2,
                  QKh + (rbase + r1) * 1024 + col1);
        cpasync16(sb + OFF_Q + 18432 + (unsigned)(r0 * 72 + s0 * 8) * 2,
                  QKl + (rbase + r0) * 1024 + col0);
        cpasync16(sb + OFF_Q + 18432 + (unsigned)(r1 * 72 + s1 * 8) * 2,
                  QKl + (rbase + r1) * 1024 + col1);
    }

#define LOAD_KV(kt, bi)                                                       \
    do {                                                                      \
        int rr = tid >> 3, ss = tid & 7;                                      \
        size_t gr = (size_t)(b << 10) + (kt) * 64 + rr;                       \
        unsigned sof = (unsigned)(rr * 72 + ss * 8) * 2;                      \
        cpasync16(sb + OFF_KV + (bi) * KVBUF + sof,                           \
                  QKh + gr * 1024 + 512 + h * 64 + ss * 8);                   \
        int v0 = tid, v1 = tid + 512;                                         \
        int vr0 = v0 >> 3, vs0 = v0 & 7, vr1 = v1 >> 3, vs1 = v1 & 7;         \
        size_t vcb = (size_t)(b << 10) + (kt) * 64;                           \
        cpasync16(sb + OFF_KV + (bi) * KVBUF + 9216 +                         \
                      (unsigned)(vr0 * 72 + vs0 * 8) * 2,                     \
                  Vh + (size_t)(h * 128 + vr0) * 16384 + vcb + vs0 * 8);      \
        cpasync16(sb + OFF_KV + (bi) * KVBUF + 9216 +                         \
                      (unsigned)(vr1 * 72 + vs1 * 8) * 2,                     \
                  Vh + (size_t)(h * 128 + vr1) * 16384 + vcb + vs1 * 8);      \
        cp_commit();                                                          \
    } while (0)

    LOAD_KV(0, 0);
    cp_wait0();

    float O[2][4][4] = {};

    for (int kt = 0; kt < NKT; kt++) {
        const int bi = kt & 1;
        if (kt) cp_wait0();
        __syncthreads();
        if (kt + 1 < NKT) LOAD_KV(kt + 1, bi ^ 1);

        const unsigned Kh = sb + OFF_KV + bi * KVBUF;
        const unsigned Vb = Kh + 9216;

        // ---- S phase: 2 terms (Qh*Kh + Ql*Kh) ----
        float acc[2][2][4] = {};
#pragma unroll
        for (int ks = 0; ks < 4; ks++) {
            const int k0 = ks * 16;
            unsigned ah[2][4], al[2][4];
#pragma unroll
            for (int mi = 0; mi < 2; mi++) {
                unsigned off = (unsigned)((wm * 32 + mi * 16 + r8 + (sub & 1) * 8) * 72 +
                                          k0 + (sub >> 1) * 8) * 2;
                ldm4(ah[mi][0], ah[mi][1], ah[mi][2], ah[mi][3], sb + OFF_Q + off);
                ldm4(al[mi][0], al[mi][1], al[mi][2], al[mi][3],
                     sb + OFF_Q + 18432 + off);
            }
            unsigned bh[2][2];
            {
                unsigned off = (unsigned)((wn * 16 + r8 + (sub >> 1) * 8) * 72 +
                                          k0 + (sub & 1) * 8) * 2;
                unsigned q0, q1, q2, q3;
                ldm4(q0, q1, q2, q3, Kh + off);
                bh[0][0] = q0; bh[0][1] = q1; bh[1][0] = q2; bh[1][1] = q3;
            }
#pragma unroll
            for (int mi = 0; mi < 2; mi++)
#pragma unroll
                for (int nf = 0; nf < 2; nf++) {
                    mma16816(acc[mi][nf], ah[mi], bh[nf]);
                    mma16816(acc[mi][nf], al[mi], bh[nf]);
                }
        }
#pragma unroll
        for (int mi = 0; mi < 2; mi++)
#pragma unroll
            for (int nf = 0; nf < 2; nf++) {
                int r0 = wm * 32 + mi * 16 + trow;
                int col = wn * 16 + nf * 8 + tcol;
                *(float2*)&Sf[r0 * 66 + col] =
                    make_float2(acc[mi][nf][0], acc[mi][nf][1]);
                *(float2*)&Sf[(r0 + 8) * 66 + col] =
                    make_float2(acc[mi][nf][2], acc[mi][nf][3]);
            }
        __syncthreads();

        // ---- online softmax ----
        {
            int r = tid >> 2, seg = tid & 3;
            float vals[16];
            float* bp = &Sf[r * 66 + seg * 16];
#pragma unroll
            for (int i = 0; i < 8; i++) {
                float2 t2 = *(float2*)(bp + 2 * i);
                vals[2 * i] = t2.x; vals[2 * i + 1] = t2.y;
            }
            float mt = vals[0];
#pragma unroll
            for (int i = 1; i < 16; i++) mt = fmaxf(mt, vals[i]);
            mt = fmaxf(mt, __shfl_xor_sync(~0u, mt, 1));
            mt = fmaxf(mt, __shfl_xor_sync(~0u, mt, 2));
            float mo = smM[r];
            float mn = fmaxf(mo, mt);
            float f = __expf(mo - mn);
            float sum = 0.f;
            __half* pp = &Pm[r * 72 + seg * 16];
#pragma unroll
            for (int i = 0; i < 8; i++) {
                float e0 = __expf(vals[2 * i] - mn);
                float e1 = __expf(vals[2 * i + 1] - mn);
                *(__half2*)(pp + 2 * i) = __floats2half2_rn(e0, e1);
                sum += e0 + e1;
            }
            sum += __shfl_xor_sync(~0u, sum, 1);
            sum += __shfl_xor_sync(~0u, sum, 2);
            if (seg == 0) {
                smM[r] = mn;
                smL[r] = smL[r] * f + sum;
                smF[r] = f;
            }
        }
        __syncthreads();

        // ---- PV phase ----
#pragma unroll
        for (int mi = 0; mi < 2; mi++) {
            float f0 = smF[wm * 32 + mi * 16 + trow];
            float f1 = smF[wm * 32 + mi * 16 + trow + 8];
#pragma unroll
            for (int nf = 0; nf < 4; nf++) {
                O[mi][nf][0] *= f0; O[mi][nf][1] *= f0;
                O[mi][nf][2] *= f1; O[mi][nf][3] *= f1;
            }
        }
#pragma unroll
        for (int ks = 0; ks < 4; ks++) {
            const int k0 = ks * 16;
            unsigned aP[2][4];
#pragma unroll
            for (int mi = 0; mi < 2; mi++) {
                unsigned off = (unsigned)((wm * 32 + mi * 16 + r8 + (sub & 1) * 8) * 72 +
                                          k0 + (sub >> 1) * 8) * 2;
                ldm4(aP[mi][0], aP[mi][1], aP[mi][2], aP[mi][3], sb + OFF_P + off);
            }
            unsigned bV[4][2];
#pragma unroll
            for (int np = 0; np < 2; np++) {
                unsigned off = (unsigned)((wn * 32 + np * 16 + r8 + (sub >> 1) * 8) * 72 +
                                          k0 + (sub & 1) * 8) * 2;
                unsigned q0, q1, q2, q3;
                ldm4(q0, q1, q2, q3, Vb + off);
                bV[np * 2][0] = q0; bV[np * 2][1] = q1;
                bV[np * 2 + 1][0] = q2; bV[np * 2 + 1][1] = q3;
            }
#pragma unroll
            for (int mi = 0; mi < 2; mi++)
#pragma unroll
                for (int nf = 0; nf < 4; nf++)
                    mma16816(O[mi][nf], aP[mi], bV[nf]);
        }
    }
#undef LOAD_KV

    // ---- epilogue: normalize, single fp16 out, split node/pos cols ----
    const long long coff = 128LL * h + 1048576LL * b;
#pragma unroll
    for (int mi = 0; mi < 2; mi++) {
        int r0 = wm * 32 + mi * 16 + trow;
        float inv0 = 1.f / smL[r0], inv1 = 1.f / smL[r0 + 8];
        int rg0 = qt * 128 + r0, rg1 = rg0 + 8;
#pragma unroll
        for (int nf = 0; nf < 4; nf++) {
            int cg = wn * 32 + nf * 8 + tcol;
            __half* base = (cg < 64) ? C0 : C1;
            int cl = cg & 63;
            *(__half2*)(base + coff + (size_t)rg0 * 1024 + cl) =
                __floats2half2_rn(O[mi][nf][0] * inv0, O[mi][nf][1] * inv0);
            *(__half2*)(base + coff + (size_t)rg1 * 1024 + cl) =
                __floats2half2_rn(O[mi][nf][2] * inv1, O[mi][nf][3] * inv1);
        }
    }
}

// ---------------------------------------------------------------------------
// Fused weight prep: blockIdx.y = task (0/1 qk n/p, 2/3 v n/p, 4/5 wo n/p)
// ---------------------------------------------------------------------------
__global__ void prep_w(const float* __restrict__ Wqn, const float* __restrict__ Wkn,
                       const float* __restrict__ Wqp, const float* __restrict__ Wkp,
                       const float* __restrict__ Wvn, const float* __restrict__ Wvp,
                       const float* __restrict__ Won, const float* __restrict__ Wop,
                       __half* __restrict__ Wqkh, __half* __restrict__ Wqkl,
                       __half* __restrict__ Wvh, __half* __restrict__ Woh) {
    int idx = blockIdx.x * blockDim.x + threadIdx.x;
    if (idx >= 524288) return;
    int task = blockIdx.y;
    int st = task & 1;
    if (task < 2) {
        const float* Wq = st ? Wqp : Wqn;
        const float* Wk = st ? Wkp : Wkn;
        int j = idx >> 9, d = idx & 511;
        int jj = j & 511;
        float v;
        if (j < 512)
            v = Wq[((size_t)((jj >> 6) * 512 + d)) * 64 + (jj & 63)] * 0.125f;
        else
            v = Wk[((size_t)((jj >> 6) * 512 + d)) * 64 + (jj & 63)];
        __half h = __float2half_rn(v);
        Wqkh[(size_t)st * WSTR + idx] = h;
        Wqkl[(size_t)st * WSTR + idx] = __float2half_rn(v - __half2float(h));
    } else if (task < 4) {
        const float* Wv = st ? Wvp : Wvn;
        int j = idx >> 9, d = idx & 511;
        Wvh[(size_t)st * WSTR + idx] =
            __float2half_rn(Wv[((size_t)((j >> 6) * 512 + d)) * 64 + (j & 63)]);
    } else {
        const float* Wo = st ? Wop : Won;
        int e = idx >> 10, j = idx & 1023;
        Woh[(size_t)st * WSTR + idx] = __float2half_rn(Wo[(size_t)j * 512 + e]);
    }
}

// ---------------------------------------------------------------------------
// Input conversion, both streams in one launch (blockIdx.y)
// ---------------------------------------------------------------------------
__global__ void cvt_pair(const float* __restrict__ Xn, const float* __restrict__ Xp,
                         __half* __restrict__ Yh, __half* __restrict__ Yl) {
    int i = blockIdx.x * blockDim.x + threadIdx.x;
    if (i >= ROWS * 512 / 4) return;
    int st = blockIdx.y;
    const float* X = st ? Xp : Xn;
    float4 v = ((const float4*)X)[i];
    __half2 h0, l0, h1, l1;
    split2(v.x, v.y, h0, l0);
    split2(v.z, v.w, h1, l1);
    uint2 uh, ul;
    uh.x = *reinterpret_cast<unsigned*>(&h0);
    uh.y = *reinterpret_cast<unsigned*>(&h1);
    ul.x = *reinterpret_cast<unsigned*>(&l0);
    ul.y = *reinterpret_cast<unsigned*>(&l1);
    ((uint2*)(Yh + (size_t)st * XSTR))[i] = uh;
    ((uint2*)(Yl + (size_t)st * XSTR))[i] = ul;
}

// ---------------------------------------------------------------------------
// Host launcher: 6 kernel launches total
// ---------------------------------------------------------------------------
extern "C" void kernel_launch(void* const* d_in, const int* in_sizes, int n_in,
                              void* d_out, int out_size) {
    const float* Xn  = (const float*)d_in[0];
    const float* Xp  = (const float*)d_in[1];
    const float* Wqn = (const float*)d_in[2];
    const float* Wqp = (const float*)d_in[3];
    const float* Wkn = (const float*)d_in[4];
    const float* Wkp = (const float*)d_in[5];
    const float* Wvn = (const float*)d_in[6];
    const float* Wvp = (const float*)d_in[7];
    const float* Won = (const float*)d_in[8];
    const float* Wop = (const float*)d_in[9];
    float* out = (float*)d_out;

    __half *Wqkh, *Wqkl, *Wvh, *Woh, *Xh, *Xl, *QKh, *QKl, *Vth, *H;
    cudaGetSymbolAddress((void**)&Wqkh, g_Wqkh);
    cudaGetSymbolAddress((void**)&Wqkl, g_Wqkl);
    cudaGetSymbolAddress((void**)&Wvh,  g_Wvh);
    cudaGetSymbolAddress((void**)&Woh,  g_Woh);
    cudaGetSymbolAddress((void**)&Xh,   g_Xh);
    cudaGetSymbolAddress((void**)&Xl,   g_Xl);
    cudaGetSymbolAddress((void**)&QKh,  g_QKh);
    cudaGetSymbolAddress((void**)&QKl,  g_QKl);
    cudaGetSymbolAddress((void**)&Vth,  g_Vth);
    cudaGetSymbolAddress((void**)&H,    g_H);

    cudaFuncSetAttribute(hgemm, cudaFuncAttributeMaxDynamicSharedMemorySize,
                         GEMM_SMEM);
    cudaFuncSetAttribute(flash_attn, cudaFuncAttributeMaxDynamicSharedMemorySize,
                         FA_SMEM);

    // 1) fused weight prep + input conversion (2 launches)
    prep_w<<<dim3(2048, 6), 256>>>(Wqn, Wkn, Wqp, Wkp, Wvn, Wvp, Won, Wop,
                                   Wqkh, Wqkl, Wvh, Woh);
    cvt_pair<<<dim3(8192, 2), 256>>>(Xn, Xp, Xh, Xl);

    // 2) Q,K projections, 3-term, pair out, both streams (z)
    hgemm<<<dim3(8, 128, 2), 512, GEMM_SMEM>>>(
        Xh, Xl, Xh, 0, XSTR, 512,
        Wqkh, Wqkh, Wqkl, 0, WSTR, 512,
        QKh, QKl, 0, QKSTR, 1024, 512, 3, 4, 0);

    // 3) V transposed, 1-term, mode 7 (remap, halfoff = 64*z), both streams
    hgemm<<<dim3(128, 8, 2), 512, GEMM_SMEM>>>(
        Wvh, nullptr, nullptr, 0, WSTR, 512,
        Xh, nullptr, nullptr, 0, XSTR, 512,
        Vth, nullptr, 0, 0, ROWS, 512, 1, 7, 64);

    // 4) fused flash attention, both softmax streams (z)
    flash_attn<<<dim3(8, 128, 2), 512, FA_SMEM>>>(
        QKh, QKl, Vth, H, H + QKSTR);

    // 5) output projections, 1-term, fp32 out, both streams (z)
    hgemm<<<dim3(4, 128, 2), 512, GEMM_SMEM>>>(
        H, nullptr, nullptr, 0, HSTR, 1024,
        Woh, nullptr, nullptr, 0, WSTR, 1024,
        out, nullptr, 0, OSTR, 512, 1024, 1, 1, 0);
}